// round 6
// baseline (speedup 1.0000x reference)
#include <cuda_runtime.h>
#include <cstdint>

#define SEQ   4096
#define HID   1280
#define NH    16
#define HD    80
#define HID3  3840
#define IMG_BLK 1024
#define ATT_SCALE 0.11180339887498949f  /* 80^-0.5 */

/* ------------ scratch (device globals: allocation-free rule) ------------- */
__device__ float    g_qkv[(size_t)SEQ * HID3];     /* qkv + bias (raw fp32)  */
__device__ uint32_t g_att[(size_t)SEQ * HID];      /* attn out, tf32-rounded */
__device__ uint32_t g_q[(size_t)NH * SEQ * HD];
__device__ uint32_t g_k[(size_t)NH * SEQ * HD];
__device__ uint32_t g_v[(size_t)NH * SEQ * HD];
__device__ uint32_t g_hid_r[(size_t)SEQ * HID];    /* rounded hidden         */
__device__ uint32_t g_wq_r[(size_t)HID3 * HID];    /* rounded qkv_w          */
__device__ uint32_t g_wp_r[(size_t)HID * HID];     /* rounded proj_w         */

/* ----------------------------- helpers ---------------------------------- */
__device__ __forceinline__ void cp_async16(void* smem, const void* gmem) {
    uint32_t s = (uint32_t)__cvta_generic_to_shared(smem);
    asm volatile("cp.async.ca.shared.global [%0], [%1], 16;\n" :: "r"(s), "l"(gmem));
}
__device__ __forceinline__ void cp_commit() {
    asm volatile("cp.async.commit_group;\n" ::: "memory");
}
__device__ __forceinline__ void cp_wait0() {
    asm volatile("cp.async.wait_group 0;\n" ::: "memory");
}
__device__ __forceinline__ void cp_wait1() {
    asm volatile("cp.async.wait_group 1;\n" ::: "memory");
}

/* m16n8k8 tf32 mma, D += A*B (fp32 accum). Operands pre-rounded +0x1000. */
__device__ __forceinline__ void mma_tf32(float* d, const uint32_t* a, const uint32_t* b) {
    asm volatile(
        "mma.sync.aligned.m16n8k8.row.col.f32.tf32.tf32.f32 "
        "{%0,%1,%2,%3}, {%4,%5,%6,%7}, {%8,%9}, {%0,%1,%2,%3};\n"
        : "+f"(d[0]), "+f"(d[1]), "+f"(d[2]), "+f"(d[3])
        : "r"(a[0]), "r"(a[1]), "r"(a[2]), "r"(a[3]),
          "r"(b[0]), "r"(b[1]));
}

/* ldmatrix x4: four 8x8 b16 tiles (= 8 rows x 16B each) */
__device__ __forceinline__ void ldsm_x4(uint32_t* r, uint32_t saddr) {
    asm volatile(
        "ldmatrix.sync.aligned.m8n8.x4.shared.b16 {%0,%1,%2,%3}, [%4];\n"
        : "=r"(r[0]), "=r"(r[1]), "=r"(r[2]), "=r"(r[3]) : "r"(saddr));
}

/* ================= tf32 pre-round: dst = bits(src) + 0x1000 ============= */
__global__ __launch_bounds__(256)
void round_kernel(const uint32_t* __restrict__ src, uint32_t* __restrict__ dst,
                  int n4)
{
    int i = blockIdx.x * 256 + threadIdx.x;
    if (i >= n4) return;
    uint4 v = ((const uint4*)src)[i];
    v.x += 0x1000u; v.y += 0x1000u; v.z += 0x1000u; v.w += 0x1000u;
    ((uint4*)dst)[i] = v;
}

/* ======================== GEMM: C = A * B^T + bias =======================
   A [M,K], B [N,K]: tf32-pre-rounded fp32 bit patterns. C [M,N] fp32.
   Block tile 128x64, BK=16, 8 warps (warp tile 32x32, grid 4m x 2n),
   ldmatrix frags, cp.async double buffer, 3 CTAs/SM (reg cap 85). */
#define GBM 128
#define GBN 64
#define GBK 16
#define GPAD 20

__global__ __launch_bounds__(256, 3)
void gemm_bias_kernel(const uint32_t* __restrict__ A, const uint32_t* __restrict__ B,
                      const float* __restrict__ bias, float* __restrict__ C,
                      int M, int N, int K)
{
    __shared__ uint32_t As[2][GBM * GPAD];
    __shared__ uint32_t Bs[2][GBN * GPAD];

    const int tid  = threadIdx.x;
    const int lane = tid & 31;
    const int warp = tid >> 5;
    const int wm   = (warp & 3) * 32;
    const int wn   = (warp >> 2) * 32;
    const int m0   = blockIdx.y * GBM;
    const int n0   = blockIdx.x * GBN;
    const int KT   = K / GBK;

    const int a_row = wm + ((lane >> 3) & 1) * 8 + (lane & 7);
    const int a_col = (lane >> 4) * 4;
    const int b_row = wn + ((lane >> 4) & 1) * 8 + (lane & 7);
    const int b_col = ((lane >> 3) & 1) * 4;

    const uint32_t As0 = (uint32_t)__cvta_generic_to_shared(&As[0][0]);
    const uint32_t Bs0 = (uint32_t)__cvta_generic_to_shared(&Bs[0][0]);

    float acc[2][4][4];
#pragma unroll
    for (int mt = 0; mt < 2; mt++)
#pragma unroll
        for (int nt = 0; nt < 4; nt++)
#pragma unroll
            for (int r = 0; r < 4; r++) acc[mt][nt][r] = 0.f;

    /* loader: A 512 chunks (2/thread), B 256 chunks (1/thread) */
    auto issue = [&](int kt, int buf) {
        int k0 = kt * GBK;
#pragma unroll
        for (int i = 0; i < 2; i++) {
            int f   = tid + i * 256;
            int row = f >> 2;
            int fc  = (f & 3) * 4;
            cp_async16(&As[buf][row * GPAD + fc], &A[(size_t)(m0 + row) * K + k0 + fc]);
        }
        {
            int row = tid >> 2;
            int fc  = (tid & 3) * 4;
            cp_async16(&Bs[buf][row * GPAD + fc], &B[(size_t)(n0 + row) * K + k0 + fc]);
        }
        cp_commit();
    };

    issue(0, 0);

#pragma unroll 1
    for (int kt = 0; kt < KT; kt++) {
        int buf = kt & 1;
        if (kt + 1 < KT) { issue(kt + 1, buf ^ 1); cp_wait1(); }
        else             { cp_wait0(); }
        __syncthreads();

        const uint32_t Ab = As0 + (uint32_t)buf * (GBM * GPAD * 4);
        const uint32_t Bb = Bs0 + (uint32_t)buf * (GBN * GPAD * 4);

#pragma unroll
        for (int ks = 0; ks < 2; ks++) {
            uint32_t a[2][4], b[2][4];
#pragma unroll
            for (int mt = 0; mt < 2; mt++)
                ldsm_x4(a[mt], Ab + (((a_row + mt * 16) * GPAD + a_col + ks * 8) << 2));
#pragma unroll
            for (int p = 0; p < 2; p++)
                ldsm_x4(b[p], Bb + (((b_row + p * 16) * GPAD + b_col + ks * 8) << 2));
#pragma unroll
            for (int mt = 0; mt < 2; mt++)
#pragma unroll
                for (int nt = 0; nt < 4; nt++)
                    mma_tf32(acc[mt][nt], a[mt], &b[nt >> 1][(nt & 1) * 2]);
        }
        __syncthreads();
    }

#pragma unroll
    for (int mt = 0; mt < 2; mt++) {
        int row = m0 + wm + mt * 16 + (lane >> 2);
#pragma unroll
        for (int nt = 0; nt < 4; nt++) {
            int col = n0 + wn + nt * 8 + (lane & 3) * 2;
            float b0 = bias[col], b1 = bias[col + 1];
            float2 v;
            v.x = acc[mt][nt][0] + b0; v.y = acc[mt][nt][1] + b1;
            *(float2*)&C[(size_t)row * N + col] = v;
            v.x = acc[mt][nt][2] + b0; v.y = acc[mt][nt][3] + b1;
            *(float2*)&C[(size_t)(row + 8) * N + col] = v;
        }
    }
}

/* ============ prep: RoPE(q)*scale, RoPE(k), v -> head-major tf32 ========= */
__global__ __launch_bounds__(256)
void prep_kernel(const float* __restrict__ qkv, const float* __restrict__ cosb,
                 const float* __restrict__ sinb)
{
    int idx = blockIdx.x * blockDim.x + threadIdx.x;
    if (idx >= SEQ * NH * HD) return;
    int d = idx % HD;
    int h = (idx / HD) % NH;
    int s = idx / (NH * HD);

    float c  = cosb[s * HD + d];
    float sn = sinb[s * HD + d];
    const float* row = qkv + (size_t)s * HID3 + h * HD;
    size_t dst = ((size_t)h * SEQ + s) * HD + d;

    {
        float x = row[d];
        float p = (d < 40) ? row[d + 40] : row[d - 40];
        float v = (d < 40) ? (x * c - p * sn) : (x * c + p * sn);
        g_q[dst] = __float_as_uint(v * ATT_SCALE) + 0x1000u;
    }
    {
        const float* rk = row + HID;
        float x = rk[d];
        float p = (d < 40) ? rk[d + 40] : rk[d - 40];
        float v = (d < 40) ? (x * c - p * sn) : (x * c + p * sn);
        g_k[dst] = __float_as_uint(v) + 0x1000u;
    }
    g_v[dst] = __float_as_uint(row[2 * HID + d]) + 0x1000u;
}

/* ===================== flash attention v2 (block-diag) =================== */
#define A2M 128
#define A2N 64
#define KVP 84
#define PPAD 68
#define SM_K(b)  (sm_u + (b) * (A2N * KVP))
#define SM_V(b)  (sm_u + (2 + (b)) * (A2N * KVP))
#define SM_P     (sm_u + 4 * (A2N * KVP))
#define ATT_SMEM ((4 * A2N * KVP + A2M * PPAD) * 4)

__global__ __launch_bounds__(256, 1)
void attn2_kernel(const uint32_t* __restrict__ gq, const uint32_t* __restrict__ gk,
                  const uint32_t* __restrict__ gv, uint32_t* __restrict__ outp)
{
    extern __shared__ uint32_t sm_u[];

    const int tid  = threadIdx.x;
    const int lane = tid & 31;
    const int warp = tid >> 5;
    const int qt   = blockIdx.x;
    const int img  = blockIdx.y;
    const int head = blockIdx.z;
    const int sq0  = img * IMG_BLK + qt * A2M;
    const int wq   = warp * 16;
    const int pr   = wq + (lane >> 2);

    {
        const uint32_t* src = gq + ((size_t)head * SEQ + sq0) * HD;
        for (int i = tid; i < A2M * (HD / 4); i += 256) {
            int r = i / (HD / 4), c4 = (i - r * (HD / 4)) * 4;
            *(uint4*)&sm_u[r * KVP + c4] = *(const uint4*)&src[r * HD + c4];
        }
    }
    __syncthreads();

    uint32_t aq[10][4];
#pragma unroll
    for (int ks = 0; ks < 10; ks++) {
        const int c = ks * 8 + (lane & 3);
        aq[ks][0] = sm_u[pr * KVP + c];
        aq[ks][1] = sm_u[(pr + 8) * KVP + c];
        aq[ks][2] = sm_u[pr * KVP + c + 4];
        aq[ks][3] = sm_u[(pr + 8) * KVP + c + 4];
    }
    __syncthreads();

    const uint32_t* kbase = gk + ((size_t)head * SEQ + img * IMG_BLK) * HD;
    const uint32_t* vbase = gv + ((size_t)head * SEQ + img * IMG_BLK) * HD;

    auto issue = [&](int jt, int b) {
        const uint32_t* ks_ = kbase + (size_t)jt * A2N * HD;
        const uint32_t* vs_ = vbase + (size_t)jt * A2N * HD;
        uint32_t* kd = SM_K(b);
        uint32_t* vd = SM_V(b);
        for (int i = tid; i < A2N * (HD / 4); i += 256) {
            int r = i / (HD / 4), c4 = (i - r * (HD / 4)) * 4;
            cp_async16(&kd[r * KVP + c4], &ks_[r * HD + c4]);
            cp_async16(&vd[r * KVP + c4], &vs_[r * HD + c4]);
        }
        cp_commit();
    };

    issue(0, 0);

    float o[10][4];
#pragma unroll
    for (int nt = 0; nt < 10; nt++)
#pragma unroll
        for (int r = 0; r < 4; r++) o[nt][r] = 0.f;
    float m0r = -1e30f, m1r = -1e30f, l0 = 0.f, l1 = 0.f;

    const int NT = IMG_BLK / A2N;
#pragma unroll 1
    for (int jt = 0; jt < NT; jt++) {
        const int buf = jt & 1;
        cp_wait0();
        __syncthreads();
        if (jt + 1 < NT) issue(jt + 1, buf ^ 1);

        const uint32_t* Kb = SM_K(buf);
        const uint32_t* Vb = SM_V(buf);

        float sacc[8][4];
#pragma unroll
        for (int nt = 0; nt < 8; nt++)
#pragma unroll
            for (int r = 0; r < 4; r++) sacc[nt][r] = 0.f;

#pragma unroll
        for (int ks = 0; ks < 10; ks++) {
            const int c = ks * 8 + (lane & 3);
#pragma unroll
            for (int nt = 0; nt < 8; nt++) {
                int n = nt * 8 + (lane >> 2);
                uint32_t bk[2];
                bk[0] = Kb[n * KVP + c];
                bk[1] = Kb[n * KVP + c + 4];
                mma_tf32(sacc[nt], aq[ks], bk);
            }
        }

        float mx0 = -1e30f, mx1 = -1e30f;
#pragma unroll
        for (int nt = 0; nt < 8; nt++) {
            mx0 = fmaxf(mx0, fmaxf(sacc[nt][0], sacc[nt][1]));
            mx1 = fmaxf(mx1, fmaxf(sacc[nt][2], sacc[nt][3]));
        }
        mx0 = fmaxf(mx0, __shfl_xor_sync(0xffffffffu, mx0, 1));
        mx0 = fmaxf(mx0, __shfl_xor_sync(0xffffffffu, mx0, 2));
        mx1 = fmaxf(mx1, __shfl_xor_sync(0xffffffffu, mx1, 1));
        mx1 = fmaxf(mx1, __shfl_xor_sync(0xffffffffu, mx1, 2));

        float mn0 = fmaxf(m0r, mx0), mn1 = fmaxf(m1r, mx1);
        float cor0 = __expf(m0r - mn0), cor1 = __expf(m1r - mn1);
        m0r = mn0; m1r = mn1;

        uint32_t* Ps = SM_P;
        float rs0 = 0.f, rs1 = 0.f;
#pragma unroll
        for (int nt = 0; nt < 8; nt++) {
            float p0 = __expf(sacc[nt][0] - mn0);
            float p1 = __expf(sacc[nt][1] - mn0);
            float p2 = __expf(sacc[nt][2] - mn1);
            float p3 = __expf(sacc[nt][3] - mn1);
            rs0 += p0 + p1;  rs1 += p2 + p3;
            int col = nt * 8 + (lane & 3) * 2;
            uint2 u01 = { __float_as_uint(p0) + 0x1000u, __float_as_uint(p1) + 0x1000u };
            *(uint2*)&Ps[pr * PPAD + col] = u01;
            uint2 u23 = { __float_as_uint(p2) + 0x1000u, __float_as_uint(p3) + 0x1000u };
            *(uint2*)&Ps[(pr + 8) * PPAD + col] = u23;
        }
        rs0 += __shfl_xor_sync(0xffffffffu, rs0, 1);
        rs0 += __shfl_xor_sync(0xffffffffu, rs0, 2);
        rs1 += __shfl_xor_sync(0xffffffffu, rs1, 1);
        rs1 += __shfl_xor_sync(0xffffffffu, rs1, 2);
        l0 = l0 * cor0 + rs0;
        l1 = l1 * cor1 + rs1;
#pragma unroll
        for (int nt = 0; nt < 10; nt++) {
            o[nt][0] *= cor0; o[nt][1] *= cor0;
            o[nt][2] *= cor1; o[nt][3] *= cor1;
        }

        __syncwarp();

#pragma unroll
        for (int ks = 0; ks < 8; ks++) {
            const int c = ks * 8 + (lane & 3);
            uint32_t ap[4];
            ap[0] = Ps[pr * PPAD + c];
            ap[1] = Ps[(pr + 8) * PPAD + c];
            ap[2] = Ps[pr * PPAD + c + 4];
            ap[3] = Ps[(pr + 8) * PPAD + c + 4];
#pragma unroll
            for (int nt = 0; nt < 10; nt++) {
                int n = nt * 8 + (lane >> 2);
                uint32_t bv[2];
                bv[0] = Vb[c * KVP + n];
                bv[1] = Vb[(c + 4) * KVP + n];
                mma_tf32(o[nt], ap, bv);
            }
        }
        __syncwarp();
    }

    /* normalize + store tf32-pre-rounded bits for the proj GEMM */
    float inv0 = 1.0f / l0, inv1 = 1.0f / l1;
    int srow = sq0 + pr;
#pragma unroll
    for (int nt = 0; nt < 10; nt++) {
        int col = head * HD + nt * 8 + (lane & 3) * 2;
        uint2 v0 = { __float_as_uint(o[nt][0] * inv0) + 0x1000u,
                     __float_as_uint(o[nt][1] * inv0) + 0x1000u };
        *(uint2*)&outp[(size_t)srow * HID + col] = v0;
        uint2 v1 = { __float_as_uint(o[nt][2] * inv1) + 0x1000u,
                     __float_as_uint(o[nt][3] * inv1) + 0x1000u };
        *(uint2*)&outp[(size_t)(srow + 8) * HID + col] = v1;
    }
}

/* ============================== launch =================================== */
extern "C" void kernel_launch(void* const* d_in, const int* in_sizes, int n_in,
                              void* d_out, int out_size)
{
    (void)in_sizes; (void)n_in; (void)out_size;
    const float* hidden = (const float*)d_in[0];
    const float* cosb   = (const float*)d_in[2];
    const float* sinb   = (const float*)d_in[3];
    const float* qkv_w  = (const float*)d_in[4];
    const float* qkv_b  = (const float*)d_in[5];
    const float* proj_w = (const float*)d_in[6];
    const float* proj_b = (const float*)d_in[7];
    float* out = (float*)d_out;

    float *qkv_ptr;
    uint32_t *att_ptr, *qp, *kp, *vp, *hid_r, *wq_r, *wp_r;
    cudaGetSymbolAddress((void**)&qkv_ptr, g_qkv);
    cudaGetSymbolAddress((void**)&att_ptr, g_att);
    cudaGetSymbolAddress((void**)&qp, g_q);
    cudaGetSymbolAddress((void**)&kp, g_k);
    cudaGetSymbolAddress((void**)&vp, g_v);
    cudaGetSymbolAddress((void**)&hid_r, g_hid_r);
    cudaGetSymbolAddress((void**)&wq_r, g_wq_r);
    cudaGetSymbolAddress((void**)&wp_r, g_wp_r);

    cudaFuncSetAttribute(attn2_kernel, cudaFuncAttributeMaxDynamicSharedMemorySize,
                         ATT_SMEM);

    /* pre-round operands (tf32 RN) */
    {
        int n4h = SEQ * HID / 4;
        round_kernel<<<(n4h + 255) / 256, 256>>>((const uint32_t*)hidden, hid_r, n4h);
        int n4q = HID3 * HID / 4;
        round_kernel<<<(n4q + 255) / 256, 256>>>((const uint32_t*)qkv_w, wq_r, n4q);
        int n4p = HID * HID / 4;
        round_kernel<<<(n4p + 255) / 256, 256>>>((const uint32_t*)proj_w, wp_r, n4p);
    }

    dim3 g1(HID3 / GBN, SEQ / GBM);
    gemm_bias_kernel<<<g1, 256>>>(hid_r, wq_r, qkv_b, qkv_ptr, SEQ, HID3, HID);

    int total = SEQ * NH * HD;
    prep_kernel<<<(total + 255) / 256, 256>>>(qkv_ptr, cosb, sinb);

    dim3 ga(IMG_BLK / A2M, 4, NH);
    attn2_kernel<<<ga, 256, ATT_SMEM>>>(qp, kp, vp, att_ptr);

    dim3 g3(HID / GBN, SEQ / GBM);
    gemm_bias_kernel<<<g3, 256>>>(att_ptr, wp_r, proj_b, out, SEQ, HID, HID);
}

// round 7
// speedup vs baseline: 1.0555x; 1.0555x over previous
#include <cuda_runtime.h>
#include <cstdint>

#define SEQ   4096
#define HID   1280
#define NH    16
#define HD    80
#define HID3  3840
#define IMG_BLK 1024
#define ATT_SCALE 0.11180339887498949f  /* 80^-0.5 */

/* ------------ scratch (device globals: allocation-free rule) ------------- */
__device__ float    g_qkv[(size_t)SEQ * HID3];     /* qkv + bias (raw fp32)  */
__device__ uint32_t g_att[(size_t)SEQ * HID];      /* attn out, tf32-rounded */
__device__ uint32_t g_q[(size_t)NH * SEQ * HD];
__device__ uint32_t g_k[(size_t)NH * SEQ * HD];
__device__ uint32_t g_v[(size_t)NH * SEQ * HD];
__device__ uint32_t g_hid_r[(size_t)SEQ * HID];    /* rounded hidden         */
__device__ uint32_t g_wq_r[(size_t)HID3 * HID];    /* rounded qkv_w          */
__device__ uint32_t g_wp_r[(size_t)HID * HID];     /* rounded proj_w         */

/* ----------------------------- helpers ---------------------------------- */
__device__ __forceinline__ void cp_async16(void* smem, const void* gmem) {
    uint32_t s = (uint32_t)__cvta_generic_to_shared(smem);
    asm volatile("cp.async.cg.shared.global [%0], [%1], 16;\n" :: "r"(s), "l"(gmem));
}
__device__ __forceinline__ void cp_commit() {
    asm volatile("cp.async.commit_group;\n" ::: "memory");
}
__device__ __forceinline__ void cp_wait0() {
    asm volatile("cp.async.wait_group 0;\n" ::: "memory");
}
__device__ __forceinline__ void cp_wait1() {
    asm volatile("cp.async.wait_group 1;\n" ::: "memory");
}

/* m16n8k8 tf32 mma, D += A*B (fp32 accum). Operands pre-rounded +0x1000. */
__device__ __forceinline__ void mma_tf32(float* d, const uint32_t* a, const uint32_t* b) {
    asm volatile(
        "mma.sync.aligned.m16n8k8.row.col.f32.tf32.tf32.f32 "
        "{%0,%1,%2,%3}, {%4,%5,%6,%7}, {%8,%9}, {%0,%1,%2,%3};\n"
        : "+f"(d[0]), "+f"(d[1]), "+f"(d[2]), "+f"(d[3])
        : "r"(a[0]), "r"(a[1]), "r"(a[2]), "r"(a[3]),
          "r"(b[0]), "r"(b[1]));
}

/* ldmatrix x4: four 8x8 b16 tiles (= 8 rows x 16B each) */
__device__ __forceinline__ void ldsm_x4(uint32_t* r, uint32_t saddr) {
    asm volatile(
        "ldmatrix.sync.aligned.m8n8.x4.shared.b16 {%0,%1,%2,%3}, [%4];\n"
        : "=r"(r[0]), "=r"(r[1]), "=r"(r[2]), "=r"(r[3]) : "r"(saddr));
}

/* ================= tf32 pre-round: dst = bits(src) + 0x1000 ============= */
__global__ __launch_bounds__(256)
void round_kernel(const uint32_t* __restrict__ src, uint32_t* __restrict__ dst,
                  int n4)
{
    int i = blockIdx.x * 256 + threadIdx.x;
    if (i >= n4) return;
    uint4 v = ((const uint4*)src)[i];
    v.x += 0x1000u; v.y += 0x1000u; v.z += 0x1000u; v.w += 0x1000u;
    ((uint4*)dst)[i] = v;
}

/* ======================== GEMM: C = A * B^T + bias =======================
   A [M,K], B [N,K]: tf32-pre-rounded fp32 bit patterns. C [M,N] fp32.
   Block tile 128x128, BK=16, 8 warps (warp tile 64x32), ldmatrix frags,
   cp.async.cg double-buffered smem, 2 CTAs/SM. */
#define GBM 128
#define GBN 128
#define GBK 16
#define GPAD 20   /* stride 80B: LDSM 8-row phase hits distinct 16B groups */

__global__ __launch_bounds__(256, 2)
void gemm_bias_kernel(const uint32_t* __restrict__ A, const uint32_t* __restrict__ B,
                      const float* __restrict__ bias, float* __restrict__ C,
                      int M, int N, int K)
{
    __shared__ uint32_t As[2][GBM * GPAD];
    __shared__ uint32_t Bs[2][GBN * GPAD];

    const int tid  = threadIdx.x;
    const int lane = tid & 31;
    const int warp = tid >> 5;
    const int wm   = (warp & 1) * 64;
    const int wn   = (warp >> 1) * 32;
    const int m0   = blockIdx.y * GBM;
    const int n0   = blockIdx.x * GBN;
    const int KT   = K / GBK;

    const int a_row = wm + ((lane >> 3) & 1) * 8 + (lane & 7);
    const int a_col = (lane >> 4) * 4;
    const int b_row = wn + ((lane >> 4) & 1) * 8 + (lane & 7);
    const int b_col = ((lane >> 3) & 1) * 4;

    const uint32_t As0 = (uint32_t)__cvta_generic_to_shared(&As[0][0]);
    const uint32_t Bs0 = (uint32_t)__cvta_generic_to_shared(&Bs[0][0]);

    float acc[4][4][4];
#pragma unroll
    for (int mt = 0; mt < 4; mt++)
#pragma unroll
        for (int nt = 0; nt < 4; nt++)
#pragma unroll
            for (int r = 0; r < 4; r++) acc[mt][nt][r] = 0.f;

    auto issue = [&](int kt, int buf) {
        int k0 = kt * GBK;
#pragma unroll
        for (int i = 0; i < 2; i++) {
            int f   = tid + i * 256;
            int row = f >> 2;
            int fc  = (f & 3) * 4;
            cp_async16(&As[buf][row * GPAD + fc], &A[(size_t)(m0 + row) * K + k0 + fc]);
            cp_async16(&Bs[buf][row * GPAD + fc], &B[(size_t)(n0 + row) * K + k0 + fc]);
        }
        cp_commit();
    };

    issue(0, 0);

#pragma unroll 1
    for (int kt = 0; kt < KT; kt++) {
        int buf = kt & 1;
        if (kt + 1 < KT) { issue(kt + 1, buf ^ 1); cp_wait1(); }
        else             { cp_wait0(); }
        __syncthreads();

        const uint32_t Ab = As0 + (uint32_t)buf * (GBM * GPAD * 4);
        const uint32_t Bb = Bs0 + (uint32_t)buf * (GBN * GPAD * 4);

#pragma unroll
        for (int ks = 0; ks < 2; ks++) {
            uint32_t a[4][4], b[2][4];
#pragma unroll
            for (int mt = 0; mt < 4; mt++)
                ldsm_x4(a[mt], Ab + (((a_row + mt * 16) * GPAD + a_col + ks * 8) << 2));
#pragma unroll
            for (int p = 0; p < 2; p++)
                ldsm_x4(b[p], Bb + (((b_row + p * 16) * GPAD + b_col + ks * 8) << 2));
#pragma unroll
            for (int mt = 0; mt < 4; mt++)
#pragma unroll
                for (int nt = 0; nt < 4; nt++)
                    mma_tf32(acc[mt][nt], a[mt], &b[nt >> 1][(nt & 1) * 2]);
        }
        __syncthreads();
    }

#pragma unroll
    for (int mt = 0; mt < 4; mt++) {
        int row = m0 + wm + mt * 16 + (lane >> 2);
#pragma unroll
        for (int nt = 0; nt < 4; nt++) {
            int col = n0 + wn + nt * 8 + (lane & 3) * 2;
            float b0 = bias[col], b1 = bias[col + 1];
            float2 v;
            v.x = acc[mt][nt][0] + b0; v.y = acc[mt][nt][1] + b1;
            *(float2*)&C[(size_t)row * N + col] = v;
            v.x = acc[mt][nt][2] + b0; v.y = acc[mt][nt][3] + b1;
            *(float2*)&C[(size_t)(row + 8) * N + col] = v;
        }
    }
}

/* ============ prep: RoPE(q)*scale, RoPE(k), v -> head-major tf32 ========= */
__global__ __launch_bounds__(256)
void prep_kernel(const float* __restrict__ qkv, const float* __restrict__ cosb,
                 const float* __restrict__ sinb)
{
    int idx = blockIdx.x * blockDim.x + threadIdx.x;
    if (idx >= SEQ * NH * HD) return;
    int d = idx % HD;
    int h = (idx / HD) % NH;
    int s = idx / (NH * HD);

    float c  = cosb[s * HD + d];
    float sn = sinb[s * HD + d];
    const float* row = qkv + (size_t)s * HID3 + h * HD;
    size_t dst = ((size_t)h * SEQ + s) * HD + d;

    {
        float x = row[d];
        float p = (d < 40) ? row[d + 40] : row[d - 40];
        float v = (d < 40) ? (x * c - p * sn) : (x * c + p * sn);
        g_q[dst] = __float_as_uint(v * ATT_SCALE) + 0x1000u;
    }
    {
        const float* rk = row + HID;
        float x = rk[d];
        float p = (d < 40) ? rk[d + 40] : rk[d - 40];
        float v = (d < 40) ? (x * c - p * sn) : (x * c + p * sn);
        g_k[dst] = __float_as_uint(v) + 0x1000u;
    }
    g_v[dst] = __float_as_uint(row[2 * HID + d]) + 0x1000u;
}

/* ===================== flash attention v2 (block-diag) =================== */
#define A2M 128
#define A2N 64
#define KVP 84
#define PPAD 68
#define SM_K(b)  (sm_u + (b) * (A2N * KVP))
#define SM_V(b)  (sm_u + (2 + (b)) * (A2N * KVP))
#define SM_P     (sm_u + 4 * (A2N * KVP))
#define ATT_SMEM ((4 * A2N * KVP + A2M * PPAD) * 4)

__global__ __launch_bounds__(256, 1)
void attn2_kernel(const uint32_t* __restrict__ gq, const uint32_t* __restrict__ gk,
                  const uint32_t* __restrict__ gv, uint32_t* __restrict__ outp)
{
    extern __shared__ uint32_t sm_u[];

    const int tid  = threadIdx.x;
    const int lane = tid & 31;
    const int warp = tid >> 5;
    const int qt   = blockIdx.x;
    const int img  = blockIdx.y;
    const int head = blockIdx.z;
    const int sq0  = img * IMG_BLK + qt * A2M;
    const int wq   = warp * 16;
    const int pr   = wq + (lane >> 2);

    {
        const uint32_t* src = gq + ((size_t)head * SEQ + sq0) * HD;
        for (int i = tid; i < A2M * (HD / 4); i += 256) {
            int r = i / (HD / 4), c4 = (i - r * (HD / 4)) * 4;
            *(uint4*)&sm_u[r * KVP + c4] = *(const uint4*)&src[r * HD + c4];
        }
    }
    __syncthreads();

    uint32_t aq[10][4];
#pragma unroll
    for (int ks = 0; ks < 10; ks++) {
        const int c = ks * 8 + (lane & 3);
        aq[ks][0] = sm_u[pr * KVP + c];
        aq[ks][1] = sm_u[(pr + 8) * KVP + c];
        aq[ks][2] = sm_u[pr * KVP + c + 4];
        aq[ks][3] = sm_u[(pr + 8) * KVP + c + 4];
    }
    __syncthreads();

    const uint32_t* kbase = gk + ((size_t)head * SEQ + img * IMG_BLK) * HD;
    const uint32_t* vbase = gv + ((size_t)head * SEQ + img * IMG_BLK) * HD;

    auto issue = [&](int jt, int b) {
        const uint32_t* ks_ = kbase + (size_t)jt * A2N * HD;
        const uint32_t* vs_ = vbase + (size_t)jt * A2N * HD;
        uint32_t* kd = SM_K(b);
        uint32_t* vd = SM_V(b);
        for (int i = tid; i < A2N * (HD / 4); i += 256) {
            int r = i / (HD / 4), c4 = (i - r * (HD / 4)) * 4;
            cp_async16(&kd[r * KVP + c4], &ks_[r * HD + c4]);
            cp_async16(&vd[r * KVP + c4], &vs_[r * HD + c4]);
        }
        cp_commit();
    };

    issue(0, 0);

    float o[10][4];
#pragma unroll
    for (int nt = 0; nt < 10; nt++)
#pragma unroll
        for (int r = 0; r < 4; r++) o[nt][r] = 0.f;
    float m0r = -1e30f, m1r = -1e30f, l0 = 0.f, l1 = 0.f;

    const int NT = IMG_BLK / A2N;
#pragma unroll 1
    for (int jt = 0; jt < NT; jt++) {
        const int buf = jt & 1;
        cp_wait0();
        __syncthreads();
        if (jt + 1 < NT) issue(jt + 1, buf ^ 1);

        const uint32_t* Kb = SM_K(buf);
        const uint32_t* Vb = SM_V(buf);

        float sacc[8][4];
#pragma unroll
        for (int nt = 0; nt < 8; nt++)
#pragma unroll
            for (int r = 0; r < 4; r++) sacc[nt][r] = 0.f;

#pragma unroll
        for (int ks = 0; ks < 10; ks++) {
            const int c = ks * 8 + (lane & 3);
#pragma unroll
            for (int nt = 0; nt < 8; nt++) {
                int n = nt * 8 + (lane >> 2);
                uint32_t bk[2];
                bk[0] = Kb[n * KVP + c];
                bk[1] = Kb[n * KVP + c + 4];
                mma_tf32(sacc[nt], aq[ks], bk);
            }
        }

        float mx0 = -1e30f, mx1 = -1e30f;
#pragma unroll
        for (int nt = 0; nt < 8; nt++) {
            mx0 = fmaxf(mx0, fmaxf(sacc[nt][0], sacc[nt][1]));
            mx1 = fmaxf(mx1, fmaxf(sacc[nt][2], sacc[nt][3]));
        }
        mx0 = fmaxf(mx0, __shfl_xor_sync(0xffffffffu, mx0, 1));
        mx0 = fmaxf(mx0, __shfl_xor_sync(0xffffffffu, mx0, 2));
        mx1 = fmaxf(mx1, __shfl_xor_sync(0xffffffffu, mx1, 1));
        mx1 = fmaxf(mx1, __shfl_xor_sync(0xffffffffu, mx1, 2));

        float mn0 = fmaxf(m0r, mx0), mn1 = fmaxf(m1r, mx1);
        float cor0 = __expf(m0r - mn0), cor1 = __expf(m1r - mn1);
        m0r = mn0; m1r = mn1;

        uint32_t* Ps = SM_P;
        float rs0 = 0.f, rs1 = 0.f;
#pragma unroll
        for (int nt = 0; nt < 8; nt++) {
            float p0 = __expf(sacc[nt][0] - mn0);
            float p1 = __expf(sacc[nt][1] - mn0);
            float p2 = __expf(sacc[nt][2] - mn1);
            float p3 = __expf(sacc[nt][3] - mn1);
            rs0 += p0 + p1;  rs1 += p2 + p3;
            int col = nt * 8 + (lane & 3) * 2;
            uint2 u01 = { __float_as_uint(p0) + 0x1000u, __float_as_uint(p1) + 0x1000u };
            *(uint2*)&Ps[pr * PPAD + col] = u01;
            uint2 u23 = { __float_as_uint(p2) + 0x1000u, __float_as_uint(p3) + 0x1000u };
            *(uint2*)&Ps[(pr + 8) * PPAD + col] = u23;
        }
        rs0 += __shfl_xor_sync(0xffffffffu, rs0, 1);
        rs0 += __shfl_xor_sync(0xffffffffu, rs0, 2);
        rs1 += __shfl_xor_sync(0xffffffffu, rs1, 1);
        rs1 += __shfl_xor_sync(0xffffffffu, rs1, 2);
        l0 = l0 * cor0 + rs0;
        l1 = l1 * cor1 + rs1;
#pragma unroll
        for (int nt = 0; nt < 10; nt++) {
            o[nt][0] *= cor0; o[nt][1] *= cor0;
            o[nt][2] *= cor1; o[nt][3] *= cor1;
        }

        __syncwarp();

#pragma unroll
        for (int ks = 0; ks < 8; ks++) {
            const int c = ks * 8 + (lane & 3);
            uint32_t ap[4];
            ap[0] = Ps[pr * PPAD + c];
            ap[1] = Ps[(pr + 8) * PPAD + c];
            ap[2] = Ps[pr * PPAD + c + 4];
            ap[3] = Ps[(pr + 8) * PPAD + c + 4];
#pragma unroll
            for (int nt = 0; nt < 10; nt++) {
                int n = nt * 8 + (lane >> 2);
                uint32_t bv[2];
                bv[0] = Vb[c * KVP + n];
                bv[1] = Vb[(c + 4) * KVP + n];
                mma_tf32(o[nt], ap, bv);
            }
        }
        __syncwarp();
    }

    /* normalize + store tf32-pre-rounded bits for the proj GEMM */
    float inv0 = 1.0f / l0, inv1 = 1.0f / l1;
    int srow = sq0 + pr;
#pragma unroll
    for (int nt = 0; nt < 10; nt++) {
        int col = head * HD + nt * 8 + (lane & 3) * 2;
        uint2 v0 = { __float_as_uint(o[nt][0] * inv0) + 0x1000u,
                     __float_as_uint(o[nt][1] * inv0) + 0x1000u };
        *(uint2*)&outp[(size_t)srow * HID + col] = v0;
        uint2 v1 = { __float_as_uint(o[nt][2] * inv1) + 0x1000u,
                     __float_as_uint(o[nt][3] * inv1) + 0x1000u };
        *(uint2*)&outp[(size_t)(srow + 8) * HID + col] = v1;
    }
}

/* ============================== launch =================================== */
extern "C" void kernel_launch(void* const* d_in, const int* in_sizes, int n_in,
                              void* d_out, int out_size)
{
    (void)in_sizes; (void)n_in; (void)out_size;
    const float* hidden = (const float*)d_in[0];
    const float* cosb   = (const float*)d_in[2];
    const float* sinb   = (const float*)d_in[3];
    const float* qkv_w  = (const float*)d_in[4];
    const float* qkv_b  = (const float*)d_in[5];
    const float* proj_w = (const float*)d_in[6];
    const float* proj_b = (const float*)d_in[7];
    float* out = (float*)d_out;

    float *qkv_ptr;
    uint32_t *att_ptr, *qp, *kp, *vp, *hid_r, *wq_r, *wp_r;
    cudaGetSymbolAddress((void**)&qkv_ptr, g_qkv);
    cudaGetSymbolAddress((void**)&att_ptr, g_att);
    cudaGetSymbolAddress((void**)&qp, g_q);
    cudaGetSymbolAddress((void**)&kp, g_k);
    cudaGetSymbolAddress((void**)&vp, g_v);
    cudaGetSymbolAddress((void**)&hid_r, g_hid_r);
    cudaGetSymbolAddress((void**)&wq_r, g_wq_r);
    cudaGetSymbolAddress((void**)&wp_r, g_wp_r);

    cudaFuncSetAttribute(attn2_kernel, cudaFuncAttributeMaxDynamicSharedMemorySize,
                         ATT_SMEM);

    /* pre-round operands (tf32 RN) */
    {
        int n4h = SEQ * HID / 4;
        round_kernel<<<(n4h + 255) / 256, 256>>>((const uint32_t*)hidden, hid_r, n4h);
        int n4q = HID3 * HID / 4;
        round_kernel<<<(n4q + 255) / 256, 256>>>((const uint32_t*)qkv_w, wq_r, n4q);
        int n4p = HID * HID / 4;
        round_kernel<<<(n4p + 255) / 256, 256>>>((const uint32_t*)proj_w, wp_r, n4p);
    }

    dim3 g1(HID3 / GBN, SEQ / GBM);
    gemm_bias_kernel<<<g1, 256>>>(hid_r, wq_r, qkv_b, qkv_ptr, SEQ, HID3, HID);

    int total = SEQ * NH * HD;
    prep_kernel<<<(total + 255) / 256, 256>>>(qkv_ptr, cosb, sinb);

    dim3 ga(IMG_BLK / A2M, 4, NH);
    attn2_kernel<<<ga, 256, ATT_SMEM>>>(qp, kp, vp, att_ptr);

    dim3 g3(HID / GBN, SEQ / GBM);
    gemm_bias_kernel<<<g3, 256>>>(att_ptr, wp_r, proj_b, out, SEQ, HID, HID);
}

// round 10
// speedup vs baseline: 1.2427x; 1.1774x over previous
#include <cuda_runtime.h>
#include <cstdint>

#define SEQ   4096
#define HID   1280
#define NH    16
#define HD    80
#define HID3  3840
#define IMG_BLK 1024
#define ATT_SCALE 0.11180339887498949f  /* 80^-0.5 */

/* ------------ scratch (device globals: allocation-free rule) ------------- */
__device__ float    g_qkv[(size_t)SEQ * HID3];     /* qkv + bias (raw fp32)  */
__device__ uint32_t g_att[(size_t)SEQ * HID];      /* attn out, tf32-rounded */
__device__ uint32_t g_q[(size_t)NH * SEQ * HD];
__device__ uint32_t g_k[(size_t)NH * SEQ * HD];
__device__ uint32_t g_v[(size_t)NH * SEQ * HD];
__device__ uint32_t g_hid_r[(size_t)SEQ * HID];    /* rounded hidden         */
__device__ uint32_t g_wq_r[(size_t)HID3 * HID];    /* rounded qkv_w          */
__device__ uint32_t g_wp_r[(size_t)HID * HID];     /* rounded proj_w         */

/* ----------------------------- helpers ---------------------------------- */
__device__ __forceinline__ void cp_async16(void* smem, const void* gmem) {
    uint32_t s = (uint32_t)__cvta_generic_to_shared(smem);
    asm volatile("cp.async.cg.shared.global [%0], [%1], 16;\n" :: "r"(s), "l"(gmem));
}
__device__ __forceinline__ void cp_commit() {
    asm volatile("cp.async.commit_group;\n" ::: "memory");
}
__device__ __forceinline__ void cp_wait0() {
    asm volatile("cp.async.wait_group 0;\n" ::: "memory");
}

/* mbarrier primitives (sm_80/90 PTX; compiles on bare compute_103) */
__device__ __forceinline__ void mbar_init(uint32_t mbar, uint32_t cnt) {
    asm volatile("mbarrier.init.shared.b64 [%0], %1;" :: "r"(mbar), "r"(cnt) : "memory");
}
__device__ __forceinline__ void mbar_arrive(uint32_t mbar) {
    asm volatile("mbarrier.arrive.shared.b64 _, [%0];" :: "r"(mbar) : "memory");
}
__device__ __forceinline__ void cpasync_arrive_noinc(uint32_t mbar) {
    asm volatile("cp.async.mbarrier.arrive.noinc.shared.b64 [%0];" :: "r"(mbar) : "memory");
}
__device__ __forceinline__ void mbar_wait(uint32_t mbar, uint32_t parity) {
    asm volatile(
        "{\n\t.reg .pred P;\n\t"
        "W_%=:\n\t"
        "mbarrier.try_wait.parity.acquire.cta.shared::cta.b64 P, [%0], %1, 0x989680;\n\t"
        "@P bra.uni D_%=;\n\t"
        "bra.uni W_%=;\n\t"
        "D_%=:\n\t}"
        :: "r"(mbar), "r"(parity) : "memory");
}

/* m16n8k8 tf32 mma, D += A*B (fp32 accum). Operands pre-rounded +0x1000. */
__device__ __forceinline__ void mma_tf32(float* d, const uint32_t* a, const uint32_t* b) {
    asm volatile(
        "mma.sync.aligned.m16n8k8.row.col.f32.tf32.tf32.f32 "
        "{%0,%1,%2,%3}, {%4,%5,%6,%7}, {%8,%9}, {%0,%1,%2,%3};\n"
        : "+f"(d[0]), "+f"(d[1]), "+f"(d[2]), "+f"(d[3])
        : "r"(a[0]), "r"(a[1]), "r"(a[2]), "r"(a[3]),
          "r"(b[0]), "r"(b[1]));
}

/* ldmatrix x4: four 8x8 b16 tiles (= 8 rows x 16B each) */
__device__ __forceinline__ void ldsm_x4(uint32_t* r, uint32_t saddr) {
    asm volatile(
        "ldmatrix.sync.aligned.m8n8.x4.shared.b16 {%0,%1,%2,%3}, [%4];\n"
        : "=r"(r[0]), "=r"(r[1]), "=r"(r[2]), "=r"(r[3]) : "r"(saddr));
}

/* ================= tf32 pre-round: dst = bits(src) + 0x1000 ============= */
__global__ __launch_bounds__(256)
void round_kernel(const uint32_t* __restrict__ src, uint32_t* __restrict__ dst,
                  int n4)
{
    int i = blockIdx.x * 256 + threadIdx.x;
    if (i >= n4) return;
    uint4 v = ((const uint4*)src)[i];
    v.x += 0x1000u; v.y += 0x1000u; v.z += 0x1000u; v.w += 0x1000u;
    ((uint4*)dst)[i] = v;
}

/* ======================== GEMM: C = A * B^T + bias =======================
   A [M,K], B [N,K]: tf32-pre-rounded fp32 bit patterns. C [M,N] fp32.
   Block tile 128x128, BK=16, 8 warps (warp tile 64x32), ldmatrix frags.
   4-stage cp.async ring with per-stage mbarriers (free-running warps, no
   __syncthreads in the mainloop -> LDSM/MMA phases overlap across warps). */
#define GBM 128
#define GBN 128
#define GBK 16
#define GPAD 20
#define GSTAGE 4
#define GS_U32  (2 * GBM * GPAD)          /* u32 per stage (A+B) = 5120     */
#define GS_BYTES (GS_U32 * 4)             /* 20480                          */
#define GBAR_OFF (GSTAGE * GS_BYTES)      /* 81920                          */
#define GEMM_SMEM (GBAR_OFF + 128)        /* 82048                          */

__global__ __launch_bounds__(256, 2)
void gemm_bias_kernel(const uint32_t* __restrict__ A, const uint32_t* __restrict__ B,
                      const float* __restrict__ bias, float* __restrict__ C,
                      int M, int N, int K)
{
    extern __shared__ uint32_t gsm[];
    const uint32_t sb = (uint32_t)__cvta_generic_to_shared(gsm);

    const int tid  = threadIdx.x;
    const int lane = tid & 31;
    const int warp = tid >> 5;
    const int wm   = (warp & 1) * 64;
    const int wn   = (warp >> 1) * 32;
    const int m0   = blockIdx.y * GBM;
    const int n0   = blockIdx.x * GBN;
    const int KT   = K / GBK;

    const int a_row = wm + ((lane >> 3) & 1) * 8 + (lane & 7);
    const int a_col = (lane >> 4) * 4;
    const int b_row = wn + ((lane >> 4) & 1) * 8 + (lane & 7);
    const int b_col = ((lane >> 3) & 1) * 4;

    /* barriers: full[s] = 256 cp.async-noinc arrivals, empty[s] = 256 arrives */
    const uint32_t fullb  = sb + GBAR_OFF;
    const uint32_t emptyb = sb + GBAR_OFF + 32;
    if (tid == 0) {
#pragma unroll
        for (int s = 0; s < GSTAGE; s++) {
            mbar_init(fullb  + s * 8, 256);
            mbar_init(emptyb + s * 8, 256);
        }
    }
    __syncthreads();

    float acc[4][4][4];
#pragma unroll
    for (int mt = 0; mt < 4; mt++)
#pragma unroll
        for (int nt = 0; nt < 4; nt++)
#pragma unroll
            for (int r = 0; r < 4; r++) acc[mt][nt][r] = 0.f;

    /* per-thread producer: 2 A-chunks + 2 B-chunks, then noinc-arrive */
    auto produce = [&](int kt, int s) {
        int k0 = kt * GBK;
        uint32_t* As = gsm + s * GS_U32;
        uint32_t* Bs = As + GBM * GPAD;
#pragma unroll
        for (int i = 0; i < 2; i++) {
            int f   = tid + i * 256;
            int row = f >> 2;
            int fc  = (f & 3) * 4;
            cp_async16(&As[row * GPAD + fc], &A[(size_t)(m0 + row) * K + k0 + fc]);
            cp_async16(&Bs[row * GPAD + fc], &B[(size_t)(n0 + row) * K + k0 + fc]);
        }
        cpasync_arrive_noinc(fullb + s * 8);
    };

    /* cursors: consumer phase starts 0, producer (empty) phase starts 1 */
    int fs = 0, fph = 0;
    int es = 0, eph = 1;

    /* prologue: fill 3 of 4 stages (4th slot = drift slack) */
    for (int pk = 0; pk < 3; pk++) {
        mbar_wait(emptyb + es * 8, eph);
        produce(pk, es);
        if (++es == GSTAGE) { es = 0; eph ^= 1; }
    }
    int pk = 3;

#pragma unroll 1
    for (int kt = 0; kt < KT; kt++) {
        mbar_wait(fullb + fs * 8, fph);

        const uint32_t Ab = sb + fs * GS_BYTES;
        const uint32_t Bb = Ab + GBM * GPAD * 4;

#pragma unroll
        for (int ks = 0; ks < 2; ks++) {
            uint32_t a[4][4], b[2][4];
#pragma unroll
            for (int mt = 0; mt < 4; mt++)
                ldsm_x4(a[mt], Ab + (((a_row + mt * 16) * GPAD + a_col + ks * 8) << 2));
#pragma unroll
            for (int p = 0; p < 2; p++)
                ldsm_x4(b[p], Bb + (((b_row + p * 16) * GPAD + b_col + ks * 8) << 2));
#pragma unroll
            for (int mt = 0; mt < 4; mt++)
#pragma unroll
                for (int nt = 0; nt < 4; nt++)
                    mma_tf32(acc[mt][nt], a[mt], &b[nt >> 1][(nt & 1) * 2]);
        }

        mbar_arrive(emptyb + fs * 8);
        if (++fs == GSTAGE) { fs = 0; fph ^= 1; }

        if (pk < KT) {
            mbar_wait(emptyb + es * 8, eph);
            produce(pk, es);
            if (++es == GSTAGE) { es = 0; eph ^= 1; }
            pk++;
        }
    }

#pragma unroll
    for (int mt = 0; mt < 4; mt++) {
        int row = m0 + wm + mt * 16 + (lane >> 2);
#pragma unroll
        for (int nt = 0; nt < 4; nt++) {
            int col = n0 + wn + nt * 8 + (lane & 3) * 2;
            float b0 = bias[col], b1 = bias[col + 1];
            float2 v;
            v.x = acc[mt][nt][0] + b0; v.y = acc[mt][nt][1] + b1;
            *(float2*)&C[(size_t)row * N + col] = v;
            v.x = acc[mt][nt][2] + b0; v.y = acc[mt][nt][3] + b1;
            *(float2*)&C[(size_t)(row + 8) * N + col] = v;
        }
    }
}

/* ============ prep: RoPE(q)*scale, RoPE(k), v -> head-major tf32 ========= */
__global__ __launch_bounds__(256)
void prep_kernel(const float* __restrict__ qkv, const float* __restrict__ cosb,
                 const float* __restrict__ sinb)
{
    int idx = blockIdx.x * blockDim.x + threadIdx.x;
    if (idx >= SEQ * NH * HD) return;
    int d = idx % HD;
    int h = (idx / HD) % NH;
    int s = idx / (NH * HD);

    float c  = cosb[s * HD + d];
    float sn = sinb[s * HD + d];
    const float* row = qkv + (size_t)s * HID3 + h * HD;
    size_t dst = ((size_t)h * SEQ + s) * HD + d;

    {
        float x = row[d];
        float p = (d < 40) ? row[d + 40] : row[d - 40];
        float v = (d < 40) ? (x * c - p * sn) : (x * c + p * sn);
        g_q[dst] = __float_as_uint(v * ATT_SCALE) + 0x1000u;
    }
    {
        const float* rk = row + HID;
        float x = rk[d];
        float p = (d < 40) ? rk[d + 40] : rk[d - 40];
        float v = (d < 40) ? (x * c - p * sn) : (x * c + p * sn);
        g_k[dst] = __float_as_uint(v) + 0x1000u;
    }
    g_v[dst] = __float_as_uint(row[2 * HID + d]) + 0x1000u;
}

/* ===================== flash attention v2 (block-diag) =================== */
#define A2M 128
#define A2N 64
#define KVP 84
#define PPAD 68
#define SM_K(b)  (sm_u + (b) * (A2N * KVP))
#define SM_V(b)  (sm_u + (2 + (b)) * (A2N * KVP))
#define SM_P     (sm_u + 4 * (A2N * KVP))
#define ATT_SMEM ((4 * A2N * KVP + A2M * PPAD) * 4)

__global__ __launch_bounds__(256, 1)
void attn2_kernel(const uint32_t* __restrict__ gq, const uint32_t* __restrict__ gk,
                  const uint32_t* __restrict__ gv, uint32_t* __restrict__ outp)
{
    extern __shared__ uint32_t sm_u[];

    const int tid  = threadIdx.x;
    const int lane = tid & 31;
    const int warp = tid >> 5;
    const int qt   = blockIdx.x;
    const int img  = blockIdx.y;
    const int head = blockIdx.z;
    const int sq0  = img * IMG_BLK + qt * A2M;
    const int wq   = warp * 16;
    const int pr   = wq + (lane >> 2);

    {
        const uint32_t* src = gq + ((size_t)head * SEQ + sq0) * HD;
        for (int i = tid; i < A2M * (HD / 4); i += 256) {
            int r = i / (HD / 4), c4 = (i - r * (HD / 4)) * 4;
            *(uint4*)&sm_u[r * KVP + c4] = *(const uint4*)&src[r * HD + c4];
        }
    }
    __syncthreads();

    uint32_t aq[10][4];
#pragma unroll
    for (int ks = 0; ks < 10; ks++) {
        const int c = ks * 8 + (lane & 3);
        aq[ks][0] = sm_u[pr * KVP + c];
        aq[ks][1] = sm_u[(pr + 8) * KVP + c];
        aq[ks][2] = sm_u[pr * KVP + c + 4];
        aq[ks][3] = sm_u[(pr + 8) * KVP + c + 4];
    }
    __syncthreads();

    const uint32_t* kbase = gk + ((size_t)head * SEQ + img * IMG_BLK) * HD;
    const uint32_t* vbase = gv + ((size_t)head * SEQ + img * IMG_BLK) * HD;

    auto issue = [&](int jt, int b) {
        const uint32_t* ks_ = kbase + (size_t)jt * A2N * HD;
        const uint32_t* vs_ = vbase + (size_t)jt * A2N * HD;
        uint32_t* kd = SM_K(b);
        uint32_t* vd = SM_V(b);
        for (int i = tid; i < A2N * (HD / 4); i += 256) {
            int r = i / (HD / 4), c4 = (i - r * (HD / 4)) * 4;
            cp_async16(&kd[r * KVP + c4], &ks_[r * HD + c4]);
            cp_async16(&vd[r * KVP + c4], &vs_[r * HD + c4]);
        }
        cp_commit();
    };

    issue(0, 0);

    float o[10][4];
#pragma unroll
    for (int nt = 0; nt < 10; nt++)
#pragma unroll
        for (int r = 0; r < 4; r++) o[nt][r] = 0.f;
    float m0r = -1e30f, m1r = -1e30f, l0 = 0.f, l1 = 0.f;

    const int NT = IMG_BLK / A2N;
#pragma unroll 1
    for (int jt = 0; jt < NT; jt++) {
        const int buf = jt & 1;
        cp_wait0();
        __syncthreads();
        if (jt + 1 < NT) issue(jt + 1, buf ^ 1);

        const uint32_t* Kb = SM_K(buf);
        const uint32_t* Vb = SM_V(buf);

        float sacc[8][4];
#pragma unroll
        for (int nt = 0; nt < 8; nt++)
#pragma unroll
            for (int r = 0; r < 4; r++) sacc[nt][r] = 0.f;

#pragma unroll
        for (int ks = 0; ks < 10; ks++) {
            const int c = ks * 8 + (lane & 3);
#pragma unroll
            for (int nt = 0; nt < 8; nt++) {
                int n = nt * 8 + (lane >> 2);
                uint32_t bk[2];
                bk[0] = Kb[n * KVP + c];
                bk[1] = Kb[n * KVP + c + 4];
                mma_tf32(sacc[nt], aq[ks], bk);
            }
        }

        float mx0 = -1e30f, mx1 = -1e30f;
#pragma unroll
        for (int nt = 0; nt < 8; nt++) {
            mx0 = fmaxf(mx0, fmaxf(sacc[nt][0], sacc[nt][1]));
            mx1 = fmaxf(mx1, fmaxf(sacc[nt][2], sacc[nt][3]));
        }
        mx0 = fmaxf(mx0, __shfl_xor_sync(0xffffffffu, mx0, 1));
        mx0 = fmaxf(mx0, __shfl_xor_sync(0xffffffffu, mx0, 2));
        mx1 = fmaxf(mx1, __shfl_xor_sync(0xffffffffu, mx1, 1));
        mx1 = fmaxf(mx1, __shfl_xor_sync(0xffffffffu, mx1, 2));

        float mn0 = fmaxf(m0r, mx0), mn1 = fmaxf(m1r, mx1);
        float cor0 = __expf(m0r - mn0), cor1 = __expf(m1r - mn1);
        m0r = mn0; m1r = mn1;

        uint32_t* Ps = SM_P;
        float rs0 = 0.f, rs1 = 0.f;
#pragma unroll
        for (int nt = 0; nt < 8; nt++) {
            float p0 = __expf(sacc[nt][0] - mn0);
            float p1 = __expf(sacc[nt][1] - mn0);
            float p2 = __expf(sacc[nt][2] - mn1);
            float p3 = __expf(sacc[nt][3] - mn1);
            rs0 += p0 + p1;  rs1 += p2 + p3;
            int col = nt * 8 + (lane & 3) * 2;
            uint2 u01 = { __float_as_uint(p0) + 0x1000u, __float_as_uint(p1) + 0x1000u };
            *(uint2*)&Ps[pr * PPAD + col] = u01;
            uint2 u23 = { __float_as_uint(p2) + 0x1000u, __float_as_uint(p3) + 0x1000u };
            *(uint2*)&Ps[(pr + 8) * PPAD + col] = u23;
        }
        rs0 += __shfl_xor_sync(0xffffffffu, rs0, 1);
        rs0 += __shfl_xor_sync(0xffffffffu, rs0, 2);
        rs1 += __shfl_xor_sync(0xffffffffu, rs1, 1);
        rs1 += __shfl_xor_sync(0xffffffffu, rs1, 2);
        l0 = l0 * cor0 + rs0;
        l1 = l1 * cor1 + rs1;
#pragma unroll
        for (int nt = 0; nt < 10; nt++) {
            o[nt][0] *= cor0; o[nt][1] *= cor0;
            o[nt][2] *= cor1; o[nt][3] *= cor1;
        }

        __syncwarp();

#pragma unroll
        for (int ks = 0; ks < 8; ks++) {
            const int c = ks * 8 + (lane & 3);
            uint32_t ap[4];
            ap[0] = Ps[pr * PPAD + c];
            ap[1] = Ps[(pr + 8) * PPAD + c];
            ap[2] = Ps[pr * PPAD + c + 4];
            ap[3] = Ps[(pr + 8) * PPAD + c + 4];
#pragma unroll
            for (int nt = 0; nt < 10; nt++) {
                int n = nt * 8 + (lane >> 2);
                uint32_t bv[2];
                bv[0] = Vb[c * KVP + n];
                bv[1] = Vb[(c + 4) * KVP + n];
                mma_tf32(o[nt], ap, bv);
            }
        }
        __syncwarp();
    }

    /* normalize + store tf32-pre-rounded bits for the proj GEMM */
    float inv0 = 1.0f / l0, inv1 = 1.0f / l1;
    int srow = sq0 + pr;
#pragma unroll
    for (int nt = 0; nt < 10; nt++) {
        int col = head * HD + nt * 8 + (lane & 3) * 2;
        uint2 v0 = { __float_as_uint(o[nt][0] * inv0) + 0x1000u,
                     __float_as_uint(o[nt][1] * inv0) + 0x1000u };
        *(uint2*)&outp[(size_t)srow * HID + col] = v0;
        uint2 v1 = { __float_as_uint(o[nt][2] * inv1) + 0x1000u,
                     __float_as_uint(o[nt][3] * inv1) + 0x1000u };
        *(uint2*)&outp[(size_t)(srow + 8) * HID + col] = v1;
    }
}

/* ============================== launch =================================== */
extern "C" void kernel_launch(void* const* d_in, const int* in_sizes, int n_in,
                              void* d_out, int out_size)
{
    (void)in_sizes; (void)n_in; (void)out_size;
    const float* hidden = (const float*)d_in[0];
    const float* cosb   = (const float*)d_in[2];
    const float* sinb   = (const float*)d_in[3];
    const float* qkv_w  = (const float*)d_in[4];
    const float* qkv_b  = (const float*)d_in[5];
    const float* proj_w = (const float*)d_in[6];
    const float* proj_b = (const float*)d_in[7];
    float* out = (float*)d_out;

    float *qkv_ptr;
    uint32_t *att_ptr, *qp, *kp, *vp, *hid_r, *wq_r, *wp_r;
    cudaGetSymbolAddress((void**)&qkv_ptr, g_qkv);
    cudaGetSymbolAddress((void**)&att_ptr, g_att);
    cudaGetSymbolAddress((void**)&qp, g_q);
    cudaGetSymbolAddress((void**)&kp, g_k);
    cudaGetSymbolAddress((void**)&vp, g_v);
    cudaGetSymbolAddress((void**)&hid_r, g_hid_r);
    cudaGetSymbolAddress((void**)&wq_r, g_wq_r);
    cudaGetSymbolAddress((void**)&wp_r, g_wp_r);

    cudaFuncSetAttribute(gemm_bias_kernel, cudaFuncAttributeMaxDynamicSharedMemorySize,
                         GEMM_SMEM);
    cudaFuncSetAttribute(attn2_kernel, cudaFuncAttributeMaxDynamicSharedMemorySize,
                         ATT_SMEM);

    /* pre-round operands (tf32 RN) */
    {
        int n4h = SEQ * HID / 4;
        round_kernel<<<(n4h + 255) / 256, 256>>>((const uint32_t*)hidden, hid_r, n4h);
        int n4q = HID3 * HID / 4;
        round_kernel<<<(n4q + 255) / 256, 256>>>((const uint32_t*)qkv_w, wq_r, n4q);
        int n4p = HID * HID / 4;
        round_kernel<<<(n4p + 255) / 256, 256>>>((const uint32_t*)proj_w, wp_r, n4p);
    }

    dim3 g1(HID3 / GBN, SEQ / GBM);
    gemm_bias_kernel<<<g1, 256, GEMM_SMEM>>>(hid_r, wq_r, qkv_b, qkv_ptr,
                                             SEQ, HID3, HID);

    int total = SEQ * NH * HD;
    prep_kernel<<<(total + 255) / 256, 256>>>(qkv_ptr, cosb, sinb);

    dim3 ga(IMG_BLK / A2M, 4, NH);
    attn2_kernel<<<ga, 256, ATT_SMEM>>>(qp, kp, vp, att_ptr);

    dim3 g3(HID / GBN, SEQ / GBM);
    gemm_bias_kernel<<<g3, 256, GEMM_SMEM>>>(att_ptr, wp_r, proj_b, out,
                                             SEQ, HID, HID);
}

// round 11
// speedup vs baseline: 1.3214x; 1.0633x over previous
#include <cuda_runtime.h>
#include <cstdint>

#define SEQ   4096
#define HID   1280
#define NH    16
#define HD    80
#define HID3  3840
#define IMG_BLK 1024
#define ATT_SCALE 0.11180339887498949f  /* 80^-0.5 */

/* ------------ scratch (device globals: allocation-free rule) ------------- */
__device__ float    g_qkv[(size_t)SEQ * HID3];     /* qkv + bias (raw fp32)  */
__device__ uint32_t g_att[(size_t)SEQ * HID];      /* attn out, tf32-rounded */
__device__ uint32_t g_q[(size_t)NH * SEQ * HD];
__device__ uint32_t g_k[(size_t)NH * SEQ * HD];
__device__ uint32_t g_v[(size_t)NH * SEQ * HD];
__device__ uint32_t g_hid_r[(size_t)SEQ * HID];    /* rounded hidden         */
__device__ uint32_t g_wq_r[(size_t)HID3 * HID];    /* rounded qkv_w          */
__device__ uint32_t g_wp_r[(size_t)HID * HID];     /* rounded proj_w         */

/* ----------------------------- helpers ---------------------------------- */
__device__ __forceinline__ void cp_async16(void* smem, const void* gmem) {
    uint32_t s = (uint32_t)__cvta_generic_to_shared(smem);
    asm volatile("cp.async.cg.shared.global [%0], [%1], 16;\n" :: "r"(s), "l"(gmem));
}

/* mbarrier primitives (sm_80/90 PTX; compiles on bare compute_103) */
__device__ __forceinline__ void mbar_init(uint32_t mbar, uint32_t cnt) {
    asm volatile("mbarrier.init.shared.b64 [%0], %1;" :: "r"(mbar), "r"(cnt) : "memory");
}
__device__ __forceinline__ void mbar_arrive(uint32_t mbar) {
    asm volatile("mbarrier.arrive.shared.b64 _, [%0];" :: "r"(mbar) : "memory");
}
__device__ __forceinline__ void cpasync_arrive_noinc(uint32_t mbar) {
    asm volatile("cp.async.mbarrier.arrive.noinc.shared.b64 [%0];" :: "r"(mbar) : "memory");
}
__device__ __forceinline__ void mbar_wait(uint32_t mbar, uint32_t parity) {
    asm volatile(
        "{\n\t.reg .pred P;\n\t"
        "W_%=:\n\t"
        "mbarrier.try_wait.parity.acquire.cta.shared::cta.b64 P, [%0], %1, 0x989680;\n\t"
        "@P bra.uni D_%=;\n\t"
        "bra.uni W_%=;\n\t"
        "D_%=:\n\t}"
        :: "r"(mbar), "r"(parity) : "memory");
}

/* m16n8k8 tf32 mma, D += A*B (fp32 accum). Operands pre-rounded +0x1000. */
__device__ __forceinline__ void mma_tf32(float* d, const uint32_t* a, const uint32_t* b) {
    asm volatile(
        "mma.sync.aligned.m16n8k8.row.col.f32.tf32.tf32.f32 "
        "{%0,%1,%2,%3}, {%4,%5,%6,%7}, {%8,%9}, {%0,%1,%2,%3};\n"
        : "+f"(d[0]), "+f"(d[1]), "+f"(d[2]), "+f"(d[3])
        : "r"(a[0]), "r"(a[1]), "r"(a[2]), "r"(a[3]),
          "r"(b[0]), "r"(b[1]));
}

/* ldmatrix x4: four 8x8 b16 tiles (= 8 rows x 16B each) */
__device__ __forceinline__ void ldsm_x4(uint32_t* r, uint32_t saddr) {
    asm volatile(
        "ldmatrix.sync.aligned.m8n8.x4.shared.b16 {%0,%1,%2,%3}, [%4];\n"
        : "=r"(r[0]), "=r"(r[1]), "=r"(r[2]), "=r"(r[3]) : "r"(saddr));
}

/* ================= tf32 pre-round: dst = bits(src) + 0x1000 ============= */
__global__ __launch_bounds__(256)
void round_kernel(const uint32_t* __restrict__ src, uint32_t* __restrict__ dst,
                  int n4)
{
    int i = blockIdx.x * 256 + threadIdx.x;
    if (i >= n4) return;
    uint4 v = ((const uint4*)src)[i];
    v.x += 0x1000u; v.y += 0x1000u; v.z += 0x1000u; v.w += 0x1000u;
    ((uint4*)dst)[i] = v;
}

/* ======================== GEMM: C = A * B^T + bias =======================
   (unchanged from round 10: 128x128 tile, BK=16, ldmatrix frags,
   4-stage cp.async ring with per-stage mbarriers, free-running warps) */
#define GBM 128
#define GBN 128
#define GBK 16
#define GPAD 20
#define GSTAGE 4
#define GS_U32  (2 * GBM * GPAD)
#define GS_BYTES (GS_U32 * 4)
#define GBAR_OFF (GSTAGE * GS_BYTES)
#define GEMM_SMEM (GBAR_OFF + 128)

__global__ __launch_bounds__(256, 2)
void gemm_bias_kernel(const uint32_t* __restrict__ A, const uint32_t* __restrict__ B,
                      const float* __restrict__ bias, float* __restrict__ C,
                      int M, int N, int K)
{
    extern __shared__ uint32_t gsm[];
    const uint32_t sb = (uint32_t)__cvta_generic_to_shared(gsm);

    const int tid  = threadIdx.x;
    const int lane = tid & 31;
    const int warp = tid >> 5;
    const int wm   = (warp & 1) * 64;
    const int wn   = (warp >> 1) * 32;
    const int m0   = blockIdx.y * GBM;
    const int n0   = blockIdx.x * GBN;
    const int KT   = K / GBK;

    const int a_row = wm + ((lane >> 3) & 1) * 8 + (lane & 7);
    const int a_col = (lane >> 4) * 4;
    const int b_row = wn + ((lane >> 4) & 1) * 8 + (lane & 7);
    const int b_col = ((lane >> 3) & 1) * 4;

    const uint32_t fullb  = sb + GBAR_OFF;
    const uint32_t emptyb = sb + GBAR_OFF + 32;
    if (tid == 0) {
#pragma unroll
        for (int s = 0; s < GSTAGE; s++) {
            mbar_init(fullb  + s * 8, 256);
            mbar_init(emptyb + s * 8, 256);
        }
    }
    __syncthreads();

    float acc[4][4][4];
#pragma unroll
    for (int mt = 0; mt < 4; mt++)
#pragma unroll
        for (int nt = 0; nt < 4; nt++)
#pragma unroll
            for (int r = 0; r < 4; r++) acc[mt][nt][r] = 0.f;

    auto produce = [&](int kt, int s) {
        int k0 = kt * GBK;
        uint32_t* As = gsm + s * GS_U32;
        uint32_t* Bs = As + GBM * GPAD;
#pragma unroll
        for (int i = 0; i < 2; i++) {
            int f   = tid + i * 256;
            int row = f >> 2;
            int fc  = (f & 3) * 4;
            cp_async16(&As[row * GPAD + fc], &A[(size_t)(m0 + row) * K + k0 + fc]);
            cp_async16(&Bs[row * GPAD + fc], &B[(size_t)(n0 + row) * K + k0 + fc]);
        }
        cpasync_arrive_noinc(fullb + s * 8);
    };

    int fs = 0, fph = 0;
    int es = 0, eph = 1;

    for (int pk = 0; pk < 3; pk++) {
        mbar_wait(emptyb + es * 8, eph);
        produce(pk, es);
        if (++es == GSTAGE) { es = 0; eph ^= 1; }
    }
    int pk = 3;

#pragma unroll 1
    for (int kt = 0; kt < KT; kt++) {
        mbar_wait(fullb + fs * 8, fph);

        const uint32_t Ab = sb + fs * GS_BYTES;
        const uint32_t Bb = Ab + GBM * GPAD * 4;

#pragma unroll
        for (int ks = 0; ks < 2; ks++) {
            uint32_t a[4][4], b[2][4];
#pragma unroll
            for (int mt = 0; mt < 4; mt++)
                ldsm_x4(a[mt], Ab + (((a_row + mt * 16) * GPAD + a_col + ks * 8) << 2));
#pragma unroll
            for (int p = 0; p < 2; p++)
                ldsm_x4(b[p], Bb + (((b_row + p * 16) * GPAD + b_col + ks * 8) << 2));
#pragma unroll
            for (int mt = 0; mt < 4; mt++)
#pragma unroll
                for (int nt = 0; nt < 4; nt++)
                    mma_tf32(acc[mt][nt], a[mt], &b[nt >> 1][(nt & 1) * 2]);
        }

        mbar_arrive(emptyb + fs * 8);
        if (++fs == GSTAGE) { fs = 0; fph ^= 1; }

        if (pk < KT) {
            mbar_wait(emptyb + es * 8, eph);
            produce(pk, es);
            if (++es == GSTAGE) { es = 0; eph ^= 1; }
            pk++;
        }
    }

#pragma unroll
    for (int mt = 0; mt < 4; mt++) {
        int row = m0 + wm + mt * 16 + (lane >> 2);
#pragma unroll
        for (int nt = 0; nt < 4; nt++) {
            int col = n0 + wn + nt * 8 + (lane & 3) * 2;
            float b0 = bias[col], b1 = bias[col + 1];
            float2 v;
            v.x = acc[mt][nt][0] + b0; v.y = acc[mt][nt][1] + b1;
            *(float2*)&C[(size_t)row * N + col] = v;
            v.x = acc[mt][nt][2] + b0; v.y = acc[mt][nt][3] + b1;
            *(float2*)&C[(size_t)(row + 8) * N + col] = v;
        }
    }
}

/* ============ prep: RoPE(q)*scale, RoPE(k), v -> head-major tf32 ========= */
__global__ __launch_bounds__(256)
void prep_kernel(const float* __restrict__ qkv, const float* __restrict__ cosb,
                 const float* __restrict__ sinb)
{
    int idx = blockIdx.x * blockDim.x + threadIdx.x;
    if (idx >= SEQ * NH * HD) return;
    int d = idx % HD;
    int h = (idx / HD) % NH;
    int s = idx / (NH * HD);

    float c  = cosb[s * HD + d];
    float sn = sinb[s * HD + d];
    const float* row = qkv + (size_t)s * HID3 + h * HD;
    size_t dst = ((size_t)h * SEQ + s) * HD + d;

    {
        float x = row[d];
        float p = (d < 40) ? row[d + 40] : row[d - 40];
        float v = (d < 40) ? (x * c - p * sn) : (x * c + p * sn);
        g_q[dst] = __float_as_uint(v * ATT_SCALE) + 0x1000u;
    }
    {
        const float* rk = row + HID;
        float x = rk[d];
        float p = (d < 40) ? rk[d + 40] : rk[d - 40];
        float v = (d < 40) ? (x * c - p * sn) : (x * c + p * sn);
        g_k[dst] = __float_as_uint(v) + 0x1000u;
    }
    g_v[dst] = __float_as_uint(row[2 * HID + d]) + 0x1000u;
}

/* ============== flash attention v3: mbarrier ring (block-diag) ===========
   grid (qtile=8, img=4, head=16), 256 threads (8 warps x 16 Q-rows).
   Q frags in registers. K/V 64-row tiles flow through a 3-stage cp.async
   ring with per-stage full/empty mbarriers — NO __syncthreads in the
   mainloop, so one warp's softmax overlaps another's MMA. P warp-private. */
#define A2M 128
#define A2N 64
#define KVP 84
#define PPAD 68
#define A3STAGE 3
#define A3S_U32 (2 * A2N * KVP)                 /* K+V per stage = 10752 u32 */
#define SM_KS(s) (sm_u + (s) * A3S_U32)
#define SM_VS(s) (sm_u + (s) * A3S_U32 + A2N * KVP)
#define SM_P     (sm_u + A3STAGE * A3S_U32)
#define ABAR_OFF ((A3STAGE * A3S_U32 + A2M * PPAD) * 4)   /* 163840 */
#define ATT_SMEM (ABAR_OFF + 64)

__global__ __launch_bounds__(256, 1)
void attn3_kernel(const uint32_t* __restrict__ gq, const uint32_t* __restrict__ gk,
                  const uint32_t* __restrict__ gv, uint32_t* __restrict__ outp)
{
    extern __shared__ uint32_t sm_u[];
    const uint32_t sb = (uint32_t)__cvta_generic_to_shared(sm_u);

    const int tid  = threadIdx.x;
    const int lane = tid & 31;
    const int warp = tid >> 5;
    const int qt   = blockIdx.x;
    const int img  = blockIdx.y;
    const int head = blockIdx.z;
    const int sq0  = img * IMG_BLK + qt * A2M;
    const int wq   = warp * 16;
    const int pr   = wq + (lane >> 2);

    const uint32_t fullb  = sb + ABAR_OFF;
    const uint32_t emptyb = sb + ABAR_OFF + 24;

    /* barrier init + Q staging (Q aliases stage 0/1 KV memory) */
    if (tid == 0) {
#pragma unroll
        for (int s = 0; s < A3STAGE; s++) {
            mbar_init(fullb  + s * 8, 256);
            mbar_init(emptyb + s * 8, 256);
        }
    }
    {
        const uint32_t* src = gq + ((size_t)head * SEQ + sq0) * HD;
        for (int i = tid; i < A2M * (HD / 4); i += 256) {
            int r = i / (HD / 4), c4 = (i - r * (HD / 4)) * 4;
            *(uint4*)&sm_u[r * KVP + c4] = *(const uint4*)&src[r * HD + c4];
        }
    }
    __syncthreads();

    uint32_t aq[10][4];
#pragma unroll
    for (int ks = 0; ks < 10; ks++) {
        const int c = ks * 8 + (lane & 3);
        aq[ks][0] = sm_u[pr * KVP + c];
        aq[ks][1] = sm_u[(pr + 8) * KVP + c];
        aq[ks][2] = sm_u[pr * KVP + c + 4];
        aq[ks][3] = sm_u[(pr + 8) * KVP + c + 4];
    }
    __syncthreads();   /* all Q frag reads done; KV ring may start */

    const uint32_t* kbase = gk + ((size_t)head * SEQ + img * IMG_BLK) * HD;
    const uint32_t* vbase = gv + ((size_t)head * SEQ + img * IMG_BLK) * HD;

    auto produce = [&](int jt, int s) {
        const uint32_t* ks_ = kbase + (size_t)jt * A2N * HD;
        const uint32_t* vs_ = vbase + (size_t)jt * A2N * HD;
        uint32_t* kd = SM_KS(s);
        uint32_t* vd = SM_VS(s);
        for (int i = tid; i < A2N * (HD / 4); i += 256) {
            int r = i / (HD / 4), c4 = (i - r * (HD / 4)) * 4;
            cp_async16(&kd[r * KVP + c4], &ks_[r * HD + c4]);
            cp_async16(&vd[r * KVP + c4], &vs_[r * HD + c4]);
        }
        cpasync_arrive_noinc(fullb + s * 8);
    };

    float o[10][4];
#pragma unroll
    for (int nt = 0; nt < 10; nt++)
#pragma unroll
        for (int r = 0; r < 4; r++) o[nt][r] = 0.f;
    float m0r = -1e30f, m1r = -1e30f, l0 = 0.f, l1 = 0.f;

    const int NT = IMG_BLK / A2N;   /* 16 */

    /* ring cursors (same convention as verified GEMM ring) */
    int fs = 0, fph = 0;
    int es = 0, eph = 1;

    /* prologue: fill 2 of 3 stages */
    for (int pj = 0; pj < 2; pj++) {
        mbar_wait(emptyb + es * 8, eph);
        produce(pj, es);
        if (++es == A3STAGE) { es = 0; eph ^= 1; }
    }
    int pj = 2;

#pragma unroll 1
    for (int jt = 0; jt < NT; jt++) {
        mbar_wait(fullb + fs * 8, fph);

        const uint32_t* Kb = SM_KS(fs);
        const uint32_t* Vb = SM_VS(fs);

        /* ---- S = Q K^T ---- */
        float sacc[8][4];
#pragma unroll
        for (int nt = 0; nt < 8; nt++)
#pragma unroll
            for (int r = 0; r < 4; r++) sacc[nt][r] = 0.f;

#pragma unroll
        for (int ks = 0; ks < 10; ks++) {
            const int c = ks * 8 + (lane & 3);
#pragma unroll
            for (int nt = 0; nt < 8; nt++) {
                int n = nt * 8 + (lane >> 2);
                uint32_t bk[2];
                bk[0] = Kb[n * KVP + c];
                bk[1] = Kb[n * KVP + c + 4];
                mma_tf32(sacc[nt], aq[ks], bk);
            }
        }

        /* ---- online softmax (rows warp-private) ---- */
        float mx0 = -1e30f, mx1 = -1e30f;
#pragma unroll
        for (int nt = 0; nt < 8; nt++) {
            mx0 = fmaxf(mx0, fmaxf(sacc[nt][0], sacc[nt][1]));
            mx1 = fmaxf(mx1, fmaxf(sacc[nt][2], sacc[nt][3]));
        }
        mx0 = fmaxf(mx0, __shfl_xor_sync(0xffffffffu, mx0, 1));
        mx0 = fmaxf(mx0, __shfl_xor_sync(0xffffffffu, mx0, 2));
        mx1 = fmaxf(mx1, __shfl_xor_sync(0xffffffffu, mx1, 1));
        mx1 = fmaxf(mx1, __shfl_xor_sync(0xffffffffu, mx1, 2));

        float mn0 = fmaxf(m0r, mx0), mn1 = fmaxf(m1r, mx1);
        float cor0 = __expf(m0r - mn0), cor1 = __expf(m1r - mn1);
        m0r = mn0; m1r = mn1;

        uint32_t* Ps = SM_P;
        float rs0 = 0.f, rs1 = 0.f;
#pragma unroll
        for (int nt = 0; nt < 8; nt++) {
            float p0 = __expf(sacc[nt][0] - mn0);
            float p1 = __expf(sacc[nt][1] - mn0);
            float p2 = __expf(sacc[nt][2] - mn1);
            float p3 = __expf(sacc[nt][3] - mn1);
            rs0 += p0 + p1;  rs1 += p2 + p3;
            int col = nt * 8 + (lane & 3) * 2;
            uint2 u01 = { __float_as_uint(p0) + 0x1000u, __float_as_uint(p1) + 0x1000u };
            *(uint2*)&Ps[pr * PPAD + col] = u01;
            uint2 u23 = { __float_as_uint(p2) + 0x1000u, __float_as_uint(p3) + 0x1000u };
            *(uint2*)&Ps[(pr + 8) * PPAD + col] = u23;
        }
        rs0 += __shfl_xor_sync(0xffffffffu, rs0, 1);
        rs0 += __shfl_xor_sync(0xffffffffu, rs0, 2);
        rs1 += __shfl_xor_sync(0xffffffffu, rs1, 1);
        rs1 += __shfl_xor_sync(0xffffffffu, rs1, 2);
        l0 = l0 * cor0 + rs0;
        l1 = l1 * cor1 + rs1;
#pragma unroll
        for (int nt = 0; nt < 10; nt++) {
            o[nt][0] *= cor0; o[nt][1] *= cor0;
            o[nt][2] *= cor1; o[nt][3] *= cor1;
        }

        __syncwarp();   /* P rows warp-private */

        /* ---- O += P V ---- */
#pragma unroll
        for (int ks = 0; ks < 8; ks++) {
            const int c = ks * 8 + (lane & 3);
            uint32_t ap[4];
            ap[0] = Ps[pr * PPAD + c];
            ap[1] = Ps[(pr + 8) * PPAD + c];
            ap[2] = Ps[pr * PPAD + c + 4];
            ap[3] = Ps[(pr + 8) * PPAD + c + 4];
#pragma unroll
            for (int nt = 0; nt < 10; nt++) {
                int n = nt * 8 + (lane >> 2);
                uint32_t bv[2];
                bv[0] = Vb[c * KVP + n];
                bv[1] = Vb[(c + 4) * KVP + n];
                mma_tf32(o[nt], ap, bv);
            }
        }
        __syncwarp();

        /* stage fully consumed (K in S-phase, V in PV-phase) */
        mbar_arrive(emptyb + fs * 8);
        if (++fs == A3STAGE) { fs = 0; fph ^= 1; }

        if (pj < NT) {
            mbar_wait(emptyb + es * 8, eph);
            produce(pj, es);
            if (++es == A3STAGE) { es = 0; eph ^= 1; }
            pj++;
        }
    }

    /* normalize + store tf32-pre-rounded bits for the proj GEMM */
    float inv0 = 1.0f / l0, inv1 = 1.0f / l1;
    int srow = sq0 + pr;
#pragma unroll
    for (int nt = 0; nt < 10; nt++) {
        int col = head * HD + nt * 8 + (lane & 3) * 2;
        uint2 v0 = { __float_as_uint(o[nt][0] * inv0) + 0x1000u,
                     __float_as_uint(o[nt][1] * inv0) + 0x1000u };
        *(uint2*)&outp[(size_t)srow * HID + col] = v0;
        uint2 v1 = { __float_as_uint(o[nt][2] * inv1) + 0x1000u,
                     __float_as_uint(o[nt][3] * inv1) + 0x1000u };
        *(uint2*)&outp[(size_t)(srow + 8) * HID + col] = v1;
    }
}

/* ============================== launch =================================== */
extern "C" void kernel_launch(void* const* d_in, const int* in_sizes, int n_in,
                              void* d_out, int out_size)
{
    (void)in_sizes; (void)n_in; (void)out_size;
    const float* hidden = (const float*)d_in[0];
    const float* cosb   = (const float*)d_in[2];
    const float* sinb   = (const float*)d_in[3];
    const float* qkv_w  = (const float*)d_in[4];
    const float* qkv_b  = (const float*)d_in[5];
    const float* proj_w = (const float*)d_in[6];
    const float* proj_b = (const float*)d_in[7];
    float* out = (float*)d_out;

    float *qkv_ptr;
    uint32_t *att_ptr, *qp, *kp, *vp, *hid_r, *wq_r, *wp_r;
    cudaGetSymbolAddress((void**)&qkv_ptr, g_qkv);
    cudaGetSymbolAddress((void**)&att_ptr, g_att);
    cudaGetSymbolAddress((void**)&qp, g_q);
    cudaGetSymbolAddress((void**)&kp, g_k);
    cudaGetSymbolAddress((void**)&vp, g_v);
    cudaGetSymbolAddress((void**)&hid_r, g_hid_r);
    cudaGetSymbolAddress((void**)&wq_r, g_wq_r);
    cudaGetSymbolAddress((void**)&wp_r, g_wp_r);

    cudaFuncSetAttribute(gemm_bias_kernel, cudaFuncAttributeMaxDynamicSharedMemorySize,
                         GEMM_SMEM);
    cudaFuncSetAttribute(attn3_kernel, cudaFuncAttributeMaxDynamicSharedMemorySize,
                         ATT_SMEM);

    /* pre-round operands (tf32 RN) */
    {
        int n4h = SEQ * HID / 4;
        round_kernel<<<(n4h + 255) / 256, 256>>>((const uint32_t*)hidden, hid_r, n4h);
        int n4q = HID3 * HID / 4;
        round_kernel<<<(n4q + 255) / 256, 256>>>((const uint32_t*)qkv_w, wq_r, n4q);
        int n4p = HID * HID / 4;
        round_kernel<<<(n4p + 255) / 256, 256>>>((const uint32_t*)proj_w, wp_r, n4p);
    }

    dim3 g1(HID3 / GBN, SEQ / GBM);
    gemm_bias_kernel<<<g1, 256, GEMM_SMEM>>>(hid_r, wq_r, qkv_b, qkv_ptr,
                                             SEQ, HID3, HID);

    int total = SEQ * NH * HD;
    prep_kernel<<<(total + 255) / 256, 256>>>(qkv_ptr, cosb, sinb);

    dim3 ga(IMG_BLK / A2M, 4, NH);
    attn3_kernel<<<ga, 256, ATT_SMEM>>>(qp, kp, vp, att_ptr);

    dim3 g3(HID / GBN, SEQ / GBM);
    gemm_bias_kernel<<<g3, 256, GEMM_SMEM>>>(att_ptr, wp_r, proj_b, out,
                                             SEQ, HID, HID);
}

// round 15
// speedup vs baseline: 1.3955x; 1.0561x over previous
#include <cuda_runtime.h>
#include <cstdint>

#define SEQ   4096
#define HID   1280
#define NH    16
#define HD    80
#define HID3  3840
#define IMG_BLK 1024
#define ATT_SCALE 0.11180339887498949f  /* 80^-0.5 */

/* ------------ scratch (device globals: allocation-free rule) ------------- */
__device__ float    g_qkv[(size_t)SEQ * HID3];     /* qkv + bias (raw fp32)  */
__device__ uint32_t g_att[(size_t)SEQ * HID];      /* attn out, tf32-rounded */
__device__ uint32_t g_q[(size_t)NH * SEQ * HD];
__device__ uint32_t g_k[(size_t)NH * SEQ * HD];
__device__ uint32_t g_vt[(size_t)NH * HD * SEQ];   /* V transposed [h][d][s] */
__device__ uint32_t g_hid_r[(size_t)SEQ * HID];    /* rounded hidden         */
__device__ uint32_t g_wq_r[(size_t)HID3 * HID];    /* rounded qkv_w          */
__device__ uint32_t g_wp_r[(size_t)HID * HID];     /* rounded proj_w         */

/* ----------------------------- helpers ---------------------------------- */
__device__ __forceinline__ void cp_async16(void* smem, const void* gmem) {
    uint32_t s = (uint32_t)__cvta_generic_to_shared(smem);
    asm volatile("cp.async.cg.shared.global [%0], [%1], 16;\n" :: "r"(s), "l"(gmem));
}

/* mbarrier primitives (sm_80/90 PTX; compiles on bare compute_103) */
__device__ __forceinline__ void mbar_init(uint32_t mbar, uint32_t cnt) {
    asm volatile("mbarrier.init.shared.b64 [%0], %1;" :: "r"(mbar), "r"(cnt) : "memory");
}
__device__ __forceinline__ void mbar_arrive(uint32_t mbar) {
    asm volatile("mbarrier.arrive.shared.b64 _, [%0];" :: "r"(mbar) : "memory");
}
__device__ __forceinline__ void cpasync_arrive_noinc(uint32_t mbar) {
    asm volatile("cp.async.mbarrier.arrive.noinc.shared.b64 [%0];" :: "r"(mbar) : "memory");
}
__device__ __forceinline__ void mbar_wait(uint32_t mbar, uint32_t parity) {
    asm volatile(
        "{\n\t.reg .pred P;\n\t"
        "W_%=:\n\t"
        "mbarrier.try_wait.parity.acquire.cta.shared::cta.b64 P, [%0], %1, 0x989680;\n\t"
        "@P bra.uni D_%=;\n\t"
        "bra.uni W_%=;\n\t"
        "D_%=:\n\t}"
        :: "r"(mbar), "r"(parity) : "memory");
}

/* m16n8k8 tf32 mma, D += A*B (fp32 accum). Operands pre-rounded +0x1000. */
__device__ __forceinline__ void mma_tf32(float* d, const uint32_t* a, const uint32_t* b) {
    asm volatile(
        "mma.sync.aligned.m16n8k8.row.col.f32.tf32.tf32.f32 "
        "{%0,%1,%2,%3}, {%4,%5,%6,%7}, {%8,%9}, {%0,%1,%2,%3};\n"
        : "+f"(d[0]), "+f"(d[1]), "+f"(d[2]), "+f"(d[3])
        : "r"(a[0]), "r"(a[1]), "r"(a[2]), "r"(a[3]),
          "r"(b[0]), "r"(b[1]));
}

/* ldmatrix x4: four 8x8 b16 tiles (= 8 rows x 16B each) */
__device__ __forceinline__ void ldsm_x4(uint32_t* r, uint32_t saddr) {
    asm volatile(
        "ldmatrix.sync.aligned.m8n8.x4.shared.b16 {%0,%1,%2,%3}, [%4];\n"
        : "=r"(r[0]), "=r"(r[1]), "=r"(r[2]), "=r"(r[3]) : "r"(saddr));
}

/* ================= tf32 pre-round: dst = bits(src) + 0x1000 ============= */
__global__ __launch_bounds__(256)
void round_kernel(const uint32_t* __restrict__ src, uint32_t* __restrict__ dst,
                  int n4)
{
    int i = blockIdx.x * 256 + threadIdx.x;
    if (i >= n4) return;
    uint4 v = ((const uint4*)src)[i];
    v.x += 0x1000u; v.y += 0x1000u; v.z += 0x1000u; v.w += 0x1000u;
    ((uint4*)dst)[i] = v;
}

/* ======================== GEMM: C = A * B^T + bias =======================
   (unchanged from round 10: 128x128 tile, BK=16, ldmatrix frags,
   4-stage cp.async ring with per-stage mbarriers, free-running warps) */
#define GBM 128
#define GBN 128
#define GBK 16
#define GPAD 20
#define GSTAGE 4
#define GS_U32  (2 * GBM * GPAD)
#define GS_BYTES (GS_U32 * 4)
#define GBAR_OFF (GSTAGE * GS_BYTES)
#define GEMM_SMEM (GBAR_OFF + 128)

__global__ __launch_bounds__(256, 2)
void gemm_bias_kernel(const uint32_t* __restrict__ A, const uint32_t* __restrict__ B,
                      const float* __restrict__ bias, float* __restrict__ C,
                      int M, int N, int K)
{
    extern __shared__ uint32_t gsm[];
    const uint32_t sb = (uint32_t)__cvta_generic_to_shared(gsm);

    const int tid  = threadIdx.x;
    const int lane = tid & 31;
    const int warp = tid >> 5;
    const int wm   = (warp & 1) * 64;
    const int wn   = (warp >> 1) * 32;
    const int m0   = blockIdx.y * GBM;
    const int n0   = blockIdx.x * GBN;
    const int KT   = K / GBK;

    const int a_row = wm + ((lane >> 3) & 1) * 8 + (lane & 7);
    const int a_col = (lane >> 4) * 4;
    const int b_row = wn + ((lane >> 4) & 1) * 8 + (lane & 7);
    const int b_col = ((lane >> 3) & 1) * 4;

    const uint32_t fullb  = sb + GBAR_OFF;
    const uint32_t emptyb = sb + GBAR_OFF + 32;
    if (tid == 0) {
#pragma unroll
        for (int s = 0; s < GSTAGE; s++) {
            mbar_init(fullb  + s * 8, 256);
            mbar_init(emptyb + s * 8, 256);
        }
    }
    __syncthreads();

    float acc[4][4][4];
#pragma unroll
    for (int mt = 0; mt < 4; mt++)
#pragma unroll
        for (int nt = 0; nt < 4; nt++)
#pragma unroll
            for (int r = 0; r < 4; r++) acc[mt][nt][r] = 0.f;

    auto produce = [&](int kt, int s) {
        int k0 = kt * GBK;
        uint32_t* As = gsm + s * GS_U32;
        uint32_t* Bs = As + GBM * GPAD;
#pragma unroll
        for (int i = 0; i < 2; i++) {
            int f   = tid + i * 256;
            int row = f >> 2;
            int fc  = (f & 3) * 4;
            cp_async16(&As[row * GPAD + fc], &A[(size_t)(m0 + row) * K + k0 + fc]);
            cp_async16(&Bs[row * GPAD + fc], &B[(size_t)(n0 + row) * K + k0 + fc]);
        }
        cpasync_arrive_noinc(fullb + s * 8);
    };

    int fs = 0, fph = 0;
    int es = 0, eph = 1;

    for (int pk = 0; pk < 3; pk++) {
        mbar_wait(emptyb + es * 8, eph);
        produce(pk, es);
        if (++es == GSTAGE) { es = 0; eph ^= 1; }
    }
    int pk = 3;

#pragma unroll 1
    for (int kt = 0; kt < KT; kt++) {
        mbar_wait(fullb + fs * 8, fph);

        const uint32_t Ab = sb + fs * GS_BYTES;
        const uint32_t Bb = Ab + GBM * GPAD * 4;

#pragma unroll
        for (int ks = 0; ks < 2; ks++) {
            uint32_t a[4][4], b[2][4];
#pragma unroll
            for (int mt = 0; mt < 4; mt++)
                ldsm_x4(a[mt], Ab + (((a_row + mt * 16) * GPAD + a_col + ks * 8) << 2));
#pragma unroll
            for (int p = 0; p < 2; p++)
                ldsm_x4(b[p], Bb + (((b_row + p * 16) * GPAD + b_col + ks * 8) << 2));
#pragma unroll
            for (int mt = 0; mt < 4; mt++)
#pragma unroll
                for (int nt = 0; nt < 4; nt++)
                    mma_tf32(acc[mt][nt], a[mt], &b[nt >> 1][(nt & 1) * 2]);
        }

        mbar_arrive(emptyb + fs * 8);
        if (++fs == GSTAGE) { fs = 0; fph ^= 1; }

        if (pk < KT) {
            mbar_wait(emptyb + es * 8, eph);
            produce(pk, es);
            if (++es == GSTAGE) { es = 0; eph ^= 1; }
            pk++;
        }
    }

#pragma unroll
    for (int mt = 0; mt < 4; mt++) {
        int row = m0 + wm + mt * 16 + (lane >> 2);
#pragma unroll
        for (int nt = 0; nt < 4; nt++) {
            int col = n0 + wn + nt * 8 + (lane & 3) * 2;
            float b0 = bias[col], b1 = bias[col + 1];
            float2 v;
            v.x = acc[mt][nt][0] + b0; v.y = acc[mt][nt][1] + b1;
            *(float2*)&C[(size_t)row * N + col] = v;
            v.x = acc[mt][nt][2] + b0; v.y = acc[mt][nt][3] + b1;
            *(float2*)&C[(size_t)(row + 8) * N + col] = v;
        }
    }
}

/* ============ prep: RoPE(q)*scale, RoPE(k) -> head-major tf32 ============ */
__global__ __launch_bounds__(256)
void prep_kernel(const float* __restrict__ qkv, const float* __restrict__ cosb,
                 const float* __restrict__ sinb)
{
    int idx = blockIdx.x * blockDim.x + threadIdx.x;
    if (idx >= SEQ * NH * HD) return;
    int d = idx % HD;
    int h = (idx / HD) % NH;
    int s = idx / (NH * HD);

    float c  = cosb[s * HD + d];
    float sn = sinb[s * HD + d];
    const float* row = qkv + (size_t)s * HID3 + h * HD;
    size_t dst = ((size_t)h * SEQ + s) * HD + d;

    {
        float x = row[d];
        float p = (d < 40) ? row[d + 40] : row[d - 40];
        float v = (d < 40) ? (x * c - p * sn) : (x * c + p * sn);
        g_q[dst] = __float_as_uint(v * ATT_SCALE) + 0x1000u;
    }
    {
        const float* rk = row + HID;
        float x = rk[d];
        float p = (d < 40) ? rk[d + 40] : rk[d - 40];
        float v = (d < 40) ? (x * c - p * sn) : (x * c + p * sn);
        g_k[dst] = __float_as_uint(v) + 0x1000u;
    }
}

/* ====== V transpose: qkv v-slice [s][h*80+d] -> g_vt [h][d][s], rounded == */
__global__ __launch_bounds__(256)
void vtrans_kernel(const float* __restrict__ qkv)
{
    __shared__ uint32_t t[32][33];
    const int tx = threadIdx.x & 31;
    const int ty = threadIdx.x >> 5;          /* 0..7 */
    const int h  = blockIdx.z;
    const int d0 = blockIdx.y * 32;
    const int s0 = blockIdx.x * 32;

#pragma unroll
    for (int j = 0; j < 4; j++) {
        int s = s0 + ty + j * 8;
        int d = d0 + tx;
        if (d < HD)
            t[ty + j * 8][tx] =
                __float_as_uint(qkv[(size_t)s * HID3 + 2 * HID + h * HD + d]) + 0x1000u;
    }
    __syncthreads();
#pragma unroll
    for (int j = 0; j < 4; j++) {
        int d = d0 + ty + j * 8;
        if (d < HD)
            g_vt[((size_t)h * HD + d) * SEQ + s0 + tx] = t[tx][ty + j * 8];
    }
}

/* ============== flash attention v4: mbarrier ring + ldmatrix =============
   grid (qtile=8, img=4, head=16), 256 threads (8 warps x 16 Q-rows).
   Q frags in registers. Per stage: K tile [64 x 80] stride 84 and
   Vt tile [80 x 64] stride 68, through a 3-stage cp.async ring.
   All fragment loads via ldmatrix (GEMM-verified lane mappings). */
#define A2M 128
#define A2N 64
#define KVP 84          /* K row stride  (21 odd -> conflict-free ldsm) */
#define VTP 68          /* Vt row stride (17 odd -> conflict-free ldsm) */
#define PPAD 68
#define A3STAGE 3
#define A3S_U32 (A2N * KVP + HD * VTP)          /* 5376 + 5440 = 10816 */
#define SM_KS(s) (sm_u + (s) * A3S_U32)
#define SM_VS(s) (sm_u + (s) * A3S_U32 + A2N * KVP)
#define SM_P     (sm_u + A3STAGE * A3S_U32)
#define ABAR_OFF ((A3STAGE * A3S_U32 + A2M * PPAD) * 4)   /* 164608 */
#define ATT_SMEM (ABAR_OFF + 64)

__global__ __launch_bounds__(256, 1)
void attn4_kernel(const uint32_t* __restrict__ gq, const uint32_t* __restrict__ gk,
                  const uint32_t* __restrict__ gvt, uint32_t* __restrict__ outp)
{
    extern __shared__ uint32_t sm_u[];
    const uint32_t sb = (uint32_t)__cvta_generic_to_shared(sm_u);

    const int tid  = threadIdx.x;
    const int lane = tid & 31;
    const int warp = tid >> 5;
    const int qt   = blockIdx.x;
    const int img  = blockIdx.y;
    const int head = blockIdx.z;
    const int sq0  = img * IMG_BLK + qt * A2M;
    const int wq   = warp * 16;
    const int pr   = wq + (lane >> 2);

    /* ldmatrix lane mappings (verified in GEMM) */
    const int bfr = ((lane >> 4) & 1) * 8 + (lane & 7);   /* B-frag row   */
    const int bfc = ((lane >> 3) & 1) * 4;                /* B-frag col   */
    const int afr = wq + ((lane >> 3) & 1) * 8 + (lane & 7); /* A-frag row */
    const int afc = (lane >> 4) * 4;                      /* A-frag col   */

    const uint32_t fullb  = sb + ABAR_OFF;
    const uint32_t emptyb = sb + ABAR_OFF + 24;

    if (tid == 0) {
#pragma unroll
        for (int s = 0; s < A3STAGE; s++) {
            mbar_init(fullb  + s * 8, 256);
            mbar_init(emptyb + s * 8, 256);
        }
    }
    /* Q staging (aliases stage-0/1 KV memory) */
    {
        const uint32_t* src = gq + ((size_t)head * SEQ + sq0) * HD;
        for (int i = tid; i < A2M * (HD / 4); i += 256) {
            int r = i / (HD / 4), c4 = (i - r * (HD / 4)) * 4;
            *(uint4*)&sm_u[r * KVP + c4] = *(const uint4*)&src[r * HD + c4];
        }
    }
    __syncthreads();

    uint32_t aq[10][4];
#pragma unroll
    for (int ks = 0; ks < 10; ks++) {
        const int c = ks * 8 + (lane & 3);
        aq[ks][0] = sm_u[pr * KVP + c];
        aq[ks][1] = sm_u[(pr + 8) * KVP + c];
        aq[ks][2] = sm_u[pr * KVP + c + 4];
        aq[ks][3] = sm_u[(pr + 8) * KVP + c + 4];
    }
    __syncthreads();   /* Q frag reads done; KV ring may start */

    const uint32_t* kbase  = gk  + ((size_t)head * SEQ + img * IMG_BLK) * HD;
    const uint32_t* vtbase = gvt + (size_t)head * HD * SEQ + img * IMG_BLK;

    auto produce = [&](int jt, int s) {
        const uint32_t* ks_ = kbase + (size_t)jt * A2N * HD;
        uint32_t* kd = SM_KS(s);
        for (int i = tid; i < A2N * (HD / 4); i += 256) {   /* 1280 chunks */
            int r = i / (HD / 4), c4 = (i - r * (HD / 4)) * 4;
            cp_async16(&kd[r * KVP + c4], &ks_[r * HD + c4]);
        }
        const uint32_t* vs_ = vtbase + (size_t)jt * A2N;
        uint32_t* vd = SM_VS(s);
        for (int i = tid; i < HD * (A2N / 4); i += 256) {   /* 1280 chunks */
            int r = i / (A2N / 4), c4 = (i - r * (A2N / 4)) * 4;
            cp_async16(&vd[r * VTP + c4], &vs_[(size_t)r * SEQ + c4]);
        }
        cpasync_arrive_noinc(fullb + s * 8);
    };

    float o[10][4];
#pragma unroll
    for (int nt = 0; nt < 10; nt++)
#pragma unroll
        for (int r = 0; r < 4; r++) o[nt][r] = 0.f;
    float m0r = -1e30f, m1r = -1e30f, l0 = 0.f, l1 = 0.f;

    const int NT = IMG_BLK / A2N;   /* 16 */

    int fs = 0, fph = 0;
    int es = 0, eph = 1;

    for (int pj = 0; pj < 2; pj++) {
        mbar_wait(emptyb + es * 8, eph);
        produce(pj, es);
        if (++es == A3STAGE) { es = 0; eph ^= 1; }
    }
    int pj = 2;

#pragma unroll 1
    for (int jt = 0; jt < NT; jt++) {
        mbar_wait(fullb + fs * 8, fph);

        const uint32_t Kbb = sb + (fs * A3S_U32) * 4;
        const uint32_t Vbb = Kbb + A2N * KVP * 4;

        /* ---- S = Q K^T (K frags via ldmatrix) ---- */
        float sacc[8][4];
#pragma unroll
        for (int nt = 0; nt < 8; nt++)
#pragma unroll
            for (int r = 0; r < 4; r++) sacc[nt][r] = 0.f;

#pragma unroll
        for (int ks = 0; ks < 10; ks++) {
#pragma unroll
            for (int p = 0; p < 4; p++) {
                uint32_t bk[4];
                ldsm_x4(bk, Kbb + (((p * 16 + bfr) * KVP + bfc + ks * 8) << 2));
                mma_tf32(sacc[2 * p],     aq[ks], bk);
                mma_tf32(sacc[2 * p + 1], aq[ks], bk + 2);
            }
        }

        /* ---- online softmax (rows warp-private) ---- */
        float mx0 = -1e30f, mx1 = -1e30f;
#pragma unroll
        for (int nt = 0; nt < 8; nt++) {
            mx0 = fmaxf(mx0, fmaxf(sacc[nt][0], sacc[nt][1]));
            mx1 = fmaxf(mx1, fmaxf(sacc[nt][2], sacc[nt][3]));
        }
        mx0 = fmaxf(mx0, __shfl_xor_sync(0xffffffffu, mx0, 1));
        mx0 = fmaxf(mx0, __shfl_xor_sync(0xffffffffu, mx0, 2));
        mx1 = fmaxf(mx1, __shfl_xor_sync(0xffffffffu, mx1, 1));
        mx1 = fmaxf(mx1, __shfl_xor_sync(0xffffffffu, mx1, 2));

        float mn0 = fmaxf(m0r, mx0), mn1 = fmaxf(m1r, mx1);
        float cor0 = __expf(m0r - mn0), cor1 = __expf(m1r - mn1);
        m0r = mn0; m1r = mn1;

        uint32_t* Ps = SM_P;
        float rs0 = 0.f, rs1 = 0.f;
#pragma unroll
        for (int nt = 0; nt < 8; nt++) {
            float p0 = __expf(sacc[nt][0] - mn0);
            float p1 = __expf(sacc[nt][1] - mn0);
            float p2 = __expf(sacc[nt][2] - mn1);
            float p3 = __expf(sacc[nt][3] - mn1);
            rs0 += p0 + p1;  rs1 += p2 + p3;
            int col = nt * 8 + (lane & 3) * 2;
            uint2 u01 = { __float_as_uint(p0) + 0x1000u, __float_as_uint(p1) + 0x1000u };
            *(uint2*)&Ps[pr * PPAD + col] = u01;
            uint2 u23 = { __float_as_uint(p2) + 0x1000u, __float_as_uint(p3) + 0x1000u };
            *(uint2*)&Ps[(pr + 8) * PPAD + col] = u23;
        }
        rs0 += __shfl_xor_sync(0xffffffffu, rs0, 1);
        rs0 += __shfl_xor_sync(0xffffffffu, rs0, 2);
        rs1 += __shfl_xor_sync(0xffffffffu, rs1, 1);
        rs1 += __shfl_xor_sync(0xffffffffu, rs1, 2);
        l0 = l0 * cor0 + rs0;
        l1 = l1 * cor1 + rs1;
#pragma unroll
        for (int nt = 0; nt < 10; nt++) {
            o[nt][0] *= cor0; o[nt][1] *= cor0;
            o[nt][2] *= cor1; o[nt][3] *= cor1;
        }

        __syncwarp();   /* P rows warp-private */

        /* ---- O += P V  (P and Vt frags via ldmatrix) ---- */
        const uint32_t Pbb = sb + (A3STAGE * A3S_U32) * 4;
#pragma unroll
        for (int ks = 0; ks < 8; ks++) {
            uint32_t ap[4];
            ldsm_x4(ap, Pbb + ((afr * PPAD + afc + ks * 8) << 2));
#pragma unroll
            for (int p = 0; p < 5; p++) {
                uint32_t bv[4];
                ldsm_x4(bv, Vbb + (((p * 16 + bfr) * VTP + bfc + ks * 8) << 2));
                mma_tf32(o[2 * p],     ap, bv);
                mma_tf32(o[2 * p + 1], ap, bv + 2);
            }
        }
        __syncwarp();

        mbar_arrive(emptyb + fs * 8);
        if (++fs == A3STAGE) { fs = 0; fph ^= 1; }

        if (pj < NT) {
            mbar_wait(emptyb + es * 8, eph);
            produce(pj, es);
            if (++es == A3STAGE) { es = 0; eph ^= 1; }
            pj++;
        }
    }

    /* normalize + store tf32-pre-rounded bits for the proj GEMM */
    float inv0 = 1.0f / l0, inv1 = 1.0f / l1;
    int srow = sq0 + pr;
#pragma unroll
    for (int nt = 0; nt < 10; nt++) {
        int col = head * HD + nt * 8 + (lane & 3) * 2;
        uint2 v0 = { __float_as_uint(o[nt][0] * inv0) + 0x1000u,
                     __float_as_uint(o[nt][1] * inv0) + 0x1000u };
        *(uint2*)&outp[(size_t)srow * HID + col] = v0;
        uint2 v1 = { __float_as_uint(o[nt][2] * inv1) + 0x1000u,
                     __float_as_uint(o[nt][3] * inv1) + 0x1000u };
        *(uint2*)&outp[(size_t)(srow + 8) * HID + col] = v1;
    }
}

/* ============================== launch =================================== */
extern "C" void kernel_launch(void* const* d_in, const int* in_sizes, int n_in,
                              void* d_out, int out_size)
{
    (void)in_sizes; (void)n_in; (void)out_size;
    const float* hidden = (const float*)d_in[0];
    const float* cosb   = (const float*)d_in[2];
    const float* sinb   = (const float*)d_in[3];
    const float* qkv_w  = (const float*)d_in[4];
    const float* qkv_b  = (const float*)d_in[5];
    const float* proj_w = (const float*)d_in[6];
    const float* proj_b = (const float*)d_in[7];
    float* out = (float*)d_out;

    float *qkv_ptr;
    uint32_t *att_ptr, *qp, *kp, *vtp, *hid_r, *wq_r, *wp_r;
    cudaGetSymbolAddress((void**)&qkv_ptr, g_qkv);
    cudaGetSymbolAddress((void**)&att_ptr, g_att);
    cudaGetSymbolAddress((void**)&qp, g_q);
    cudaGetSymbolAddress((void**)&kp, g_k);
    cudaGetSymbolAddress((void**)&vtp, g_vt);
    cudaGetSymbolAddress((void**)&hid_r, g_hid_r);
    cudaGetSymbolAddress((void**)&wq_r, g_wq_r);
    cudaGetSymbolAddress((void**)&wp_r, g_wp_r);

    cudaFuncSetAttribute(gemm_bias_kernel, cudaFuncAttributeMaxDynamicSharedMemorySize,
                         GEMM_SMEM);
    cudaFuncSetAttribute(attn4_kernel, cudaFuncAttributeMaxDynamicSharedMemorySize,
                         ATT_SMEM);

    /* pre-round operands (tf32 RN) */
    {
        int n4h = SEQ * HID / 4;
        round_kernel<<<(n4h + 255) / 256, 256>>>((const uint32_t*)hidden, hid_r, n4h);
        int n4q = HID3 * HID / 4;
        round_kernel<<<(n4q + 255) / 256, 256>>>((const uint32_t*)qkv_w, wq_r, n4q);
        int n4p = HID * HID / 4;
        round_kernel<<<(n4p + 255) / 256, 256>>>((const uint32_t*)proj_w, wp_r, n4p);
    }

    dim3 g1(HID3 / GBN, SEQ / GBM);
    gemm_bias_kernel<<<g1, 256, GEMM_SMEM>>>(hid_r, wq_r, qkv_b, qkv_ptr,
                                             SEQ, HID3, HID);

    int total = SEQ * NH * HD;
    prep_kernel<<<(total + 255) / 256, 256>>>(qkv_ptr, cosb, sinb);

    dim3 gv(SEQ / 32, (HD + 31) / 32, NH);
    vtrans_kernel<<<gv, 256>>>(qkv_ptr);

    dim3 ga(IMG_BLK / A2M, 4, NH);
    attn4_kernel<<<ga, 256, ATT_SMEM>>>(qp, kp, vtp, att_ptr);

    dim3 g3(HID / GBN, SEQ / GBM);
    gemm_bias_kernel<<<g3, 256, GEMM_SMEM>>>(att_ptr, wp_r, proj_b, out,
                                             SEQ, HID, HID);
}

// round 16
// speedup vs baseline: 1.4572x; 1.0442x over previous
#include <cuda_runtime.h>
#include <cstdint>

#define SEQ   4096
#define HID   1280
#define NH    16
#define HD    80
#define HID3  3840
#define IMG_BLK 1024
#define ATT_SCALE 0.11180339887498949f  /* 80^-0.5 */

/* ------------ scratch (device globals: allocation-free rule) ------------- */
__device__ float    g_qkv[(size_t)SEQ * HID3];     /* qkv + bias (raw fp32)  */
__device__ uint32_t g_att[(size_t)SEQ * HID];      /* attn out, tf32-rounded */
__device__ uint32_t g_q[(size_t)NH * SEQ * HD];
__device__ uint32_t g_k[(size_t)NH * SEQ * HD];
__device__ uint32_t g_vt[(size_t)NH * HD * SEQ];   /* V transposed [h][d][s] */
__device__ uint32_t g_hid_r[(size_t)SEQ * HID];    /* rounded hidden         */
__device__ uint32_t g_wq_r[(size_t)HID3 * HID];    /* rounded qkv_w          */
__device__ uint32_t g_wp_r[(size_t)HID * HID];     /* rounded proj_w         */

/* ----------------------------- helpers ---------------------------------- */
__device__ __forceinline__ void cp_async16(void* smem, const void* gmem) {
    uint32_t s = (uint32_t)__cvta_generic_to_shared(smem);
    asm volatile("cp.async.cg.shared.global [%0], [%1], 16;\n" :: "r"(s), "l"(gmem));
}

/* mbarrier primitives (sm_80/90 PTX; compiles on bare compute_103) */
__device__ __forceinline__ void mbar_init(uint32_t mbar, uint32_t cnt) {
    asm volatile("mbarrier.init.shared.b64 [%0], %1;" :: "r"(mbar), "r"(cnt) : "memory");
}
__device__ __forceinline__ void mbar_arrive(uint32_t mbar) {
    asm volatile("mbarrier.arrive.shared.b64 _, [%0];" :: "r"(mbar) : "memory");
}
__device__ __forceinline__ void cpasync_arrive_noinc(uint32_t mbar) {
    asm volatile("cp.async.mbarrier.arrive.noinc.shared.b64 [%0];" :: "r"(mbar) : "memory");
}
__device__ __forceinline__ void mbar_wait(uint32_t mbar, uint32_t parity) {
    asm volatile(
        "{\n\t.reg .pred P;\n\t"
        "W_%=:\n\t"
        "mbarrier.try_wait.parity.acquire.cta.shared::cta.b64 P, [%0], %1, 0x989680;\n\t"
        "@P bra.uni D_%=;\n\t"
        "bra.uni W_%=;\n\t"
        "D_%=:\n\t}"
        :: "r"(mbar), "r"(parity) : "memory");
}

/* m16n8k8 tf32 mma, D += A*B (fp32 accum). Operands pre-rounded +0x1000. */
__device__ __forceinline__ void mma_tf32(float* d, const uint32_t* a, const uint32_t* b) {
    asm volatile(
        "mma.sync.aligned.m16n8k8.row.col.f32.tf32.tf32.f32 "
        "{%0,%1,%2,%3}, {%4,%5,%6,%7}, {%8,%9}, {%0,%1,%2,%3};\n"
        : "+f"(d[0]), "+f"(d[1]), "+f"(d[2]), "+f"(d[3])
        : "r"(a[0]), "r"(a[1]), "r"(a[2]), "r"(a[3]),
          "r"(b[0]), "r"(b[1]));
}

/* ldmatrix x4: four 8x8 b16 tiles (= 8 rows x 16B each) */
__device__ __forceinline__ void ldsm_x4(uint32_t* r, uint32_t saddr) {
    asm volatile(
        "ldmatrix.sync.aligned.m8n8.x4.shared.b16 {%0,%1,%2,%3}, [%4];\n"
        : "=r"(r[0]), "=r"(r[1]), "=r"(r[2]), "=r"(r[3]) : "r"(saddr));
}

/* ========== tf32 pre-round (fused): hidden + qkv_w + proj_w ============= */
#define RN1 (SEQ * HID / 4)
#define RN2 (RN1 + HID3 * HID / 4)
#define RN3 (RN2 + HID * HID / 4)
__global__ __launch_bounds__(256)
void round_all_kernel(const uint32_t* __restrict__ hid,
                      const uint32_t* __restrict__ wq,
                      const uint32_t* __restrict__ wp,
                      uint32_t* __restrict__ hid_r,
                      uint32_t* __restrict__ wq_r,
                      uint32_t* __restrict__ wp_r)
{
    int i = blockIdx.x * 256 + threadIdx.x;
    if (i >= RN3) return;
    const uint32_t* src;
    uint32_t* dst;
    int j;
    if (i < RN1)      { src = hid; dst = hid_r; j = i; }
    else if (i < RN2) { src = wq;  dst = wq_r;  j = i - RN1; }
    else              { src = wp;  dst = wp_r;  j = i - RN2; }
    uint4 v = ((const uint4*)src)[j];
    v.x += 0x1000u; v.y += 0x1000u; v.z += 0x1000u; v.w += 0x1000u;
    ((uint4*)dst)[j] = v;
}

/* ======================== GEMM: C = A * B^T + bias =======================
   (unchanged: 128x128 tile, BK=16, ldmatrix frags, 4-stage cp.async
   mbarrier ring, free-running warps, 2 CTAs/SM) */
#define GBM 128
#define GBN 128
#define GBK 16
#define GPAD 20
#define GSTAGE 4
#define GS_U32  (2 * GBM * GPAD)
#define GS_BYTES (GS_U32 * 4)
#define GBAR_OFF (GSTAGE * GS_BYTES)
#define GEMM_SMEM (GBAR_OFF + 128)

__global__ __launch_bounds__(256, 2)
void gemm_bias_kernel(const uint32_t* __restrict__ A, const uint32_t* __restrict__ B,
                      const float* __restrict__ bias, float* __restrict__ C,
                      int M, int N, int K)
{
    extern __shared__ uint32_t gsm[];
    const uint32_t sb = (uint32_t)__cvta_generic_to_shared(gsm);

    const int tid  = threadIdx.x;
    const int lane = tid & 31;
    const int warp = tid >> 5;
    const int wm   = (warp & 1) * 64;
    const int wn   = (warp >> 1) * 32;
    const int m0   = blockIdx.y * GBM;
    const int n0   = blockIdx.x * GBN;
    const int KT   = K / GBK;

    const int a_row = wm + ((lane >> 3) & 1) * 8 + (lane & 7);
    const int a_col = (lane >> 4) * 4;
    const int b_row = wn + ((lane >> 4) & 1) * 8 + (lane & 7);
    const int b_col = ((lane >> 3) & 1) * 4;

    const uint32_t fullb  = sb + GBAR_OFF;
    const uint32_t emptyb = sb + GBAR_OFF + 32;
    if (tid == 0) {
#pragma unroll
        for (int s = 0; s < GSTAGE; s++) {
            mbar_init(fullb  + s * 8, 256);
            mbar_init(emptyb + s * 8, 256);
        }
    }
    __syncthreads();

    float acc[4][4][4];
#pragma unroll
    for (int mt = 0; mt < 4; mt++)
#pragma unroll
        for (int nt = 0; nt < 4; nt++)
#pragma unroll
            for (int r = 0; r < 4; r++) acc[mt][nt][r] = 0.f;

    auto produce = [&](int kt, int s) {
        int k0 = kt * GBK;
        uint32_t* As = gsm + s * GS_U32;
        uint32_t* Bs = As + GBM * GPAD;
#pragma unroll
        for (int i = 0; i < 2; i++) {
            int f   = tid + i * 256;
            int row = f >> 2;
            int fc  = (f & 3) * 4;
            cp_async16(&As[row * GPAD + fc], &A[(size_t)(m0 + row) * K + k0 + fc]);
            cp_async16(&Bs[row * GPAD + fc], &B[(size_t)(n0 + row) * K + k0 + fc]);
        }
        cpasync_arrive_noinc(fullb + s * 8);
    };

    int fs = 0, fph = 0;
    int es = 0, eph = 1;

    for (int pk = 0; pk < 3; pk++) {
        mbar_wait(emptyb + es * 8, eph);
        produce(pk, es);
        if (++es == GSTAGE) { es = 0; eph ^= 1; }
    }
    int pk = 3;

#pragma unroll 1
    for (int kt = 0; kt < KT; kt++) {
        mbar_wait(fullb + fs * 8, fph);

        const uint32_t Ab = sb + fs * GS_BYTES;
        const uint32_t Bb = Ab + GBM * GPAD * 4;

#pragma unroll
        for (int ks = 0; ks < 2; ks++) {
            uint32_t a[4][4], b[2][4];
#pragma unroll
            for (int mt = 0; mt < 4; mt++)
                ldsm_x4(a[mt], Ab + (((a_row + mt * 16) * GPAD + a_col + ks * 8) << 2));
#pragma unroll
            for (int p = 0; p < 2; p++)
                ldsm_x4(b[p], Bb + (((b_row + p * 16) * GPAD + b_col + ks * 8) << 2));
#pragma unroll
            for (int mt = 0; mt < 4; mt++)
#pragma unroll
                for (int nt = 0; nt < 4; nt++)
                    mma_tf32(acc[mt][nt], a[mt], &b[nt >> 1][(nt & 1) * 2]);
        }

        mbar_arrive(emptyb + fs * 8);
        if (++fs == GSTAGE) { fs = 0; fph ^= 1; }

        if (pk < KT) {
            mbar_wait(emptyb + es * 8, eph);
            produce(pk, es);
            if (++es == GSTAGE) { es = 0; eph ^= 1; }
            pk++;
        }
    }

#pragma unroll
    for (int mt = 0; mt < 4; mt++) {
        int row = m0 + wm + mt * 16 + (lane >> 2);
#pragma unroll
        for (int nt = 0; nt < 4; nt++) {
            int col = n0 + wn + nt * 8 + (lane & 3) * 2;
            float b0 = bias[col], b1 = bias[col + 1];
            float2 v;
            v.x = acc[mt][nt][0] + b0; v.y = acc[mt][nt][1] + b1;
            *(float2*)&C[(size_t)row * N + col] = v;
            v.x = acc[mt][nt][2] + b0; v.y = acc[mt][nt][3] + b1;
            *(float2*)&C[(size_t)(row + 8) * N + col] = v;
        }
    }
}

/* ============ prep: RoPE(q)*scale, RoPE(k) -> head-major tf32 ============ */
__global__ __launch_bounds__(256)
void prep_kernel(const float* __restrict__ qkv, const float* __restrict__ cosb,
                 const float* __restrict__ sinb)
{
    int idx = blockIdx.x * blockDim.x + threadIdx.x;
    if (idx >= SEQ * NH * HD) return;
    int d = idx % HD;
    int h = (idx / HD) % NH;
    int s = idx / (NH * HD);

    float c  = cosb[s * HD + d];
    float sn = sinb[s * HD + d];
    const float* row = qkv + (size_t)s * HID3 + h * HD;
    size_t dst = ((size_t)h * SEQ + s) * HD + d;

    {
        float x = row[d];
        float p = (d < 40) ? row[d + 40] : row[d - 40];
        float v = (d < 40) ? (x * c - p * sn) : (x * c + p * sn);
        g_q[dst] = __float_as_uint(v * ATT_SCALE) + 0x1000u;
    }
    {
        const float* rk = row + HID;
        float x = rk[d];
        float p = (d < 40) ? rk[d + 40] : rk[d - 40];
        float v = (d < 40) ? (x * c - p * sn) : (x * c + p * sn);
        g_k[dst] = __float_as_uint(v) + 0x1000u;
    }
}

/* ====== V transpose: qkv v-slice [s][h*80+d] -> g_vt [h][d][s], rounded == */
__global__ __launch_bounds__(256)
void vtrans_kernel(const float* __restrict__ qkv)
{
    __shared__ uint32_t t[32][33];
    const int tx = threadIdx.x & 31;
    const int ty = threadIdx.x >> 5;          /* 0..7 */
    const int h  = blockIdx.z;
    const int d0 = blockIdx.y * 32;
    const int s0 = blockIdx.x * 32;

#pragma unroll
    for (int j = 0; j < 4; j++) {
        int s = s0 + ty + j * 8;
        int d = d0 + tx;
        if (d < HD)
            t[ty + j * 8][tx] =
                __float_as_uint(qkv[(size_t)s * HID3 + 2 * HID + h * HD + d]) + 0x1000u;
    }
    __syncthreads();
#pragma unroll
    for (int j = 0; j < 4; j++) {
        int d = d0 + ty + j * 8;
        if (d < HD)
            g_vt[((size_t)h * HD + d) * SEQ + s0 + tx] = t[tx][ty + j * 8];
    }
}

/* ============== flash attention v5: 512-thread CTA, mbarrier ring ========
   grid (qtile=4, img=4, head=16), 512 threads (16 warps x 16 Q-rows =
   256 q-rows per CTA -> 16 warps/SM occupancy, KV traffic halved).
   K/Vt tiles through a 3-stage cp.async ring; all frag loads via
   ldmatrix (GEMM-verified lane mappings). No __syncthreads in mainloop. */
#define A2M 256
#define A2N 64
#define KVP 84          /* K row stride  (21x16B, odd -> conflict-free)  */
#define VTP 68          /* Vt row stride (17x16B, odd -> conflict-free)  */
#define PPAD 68
#define A3STAGE 3
#define A3S_U32 (A2N * KVP + HD * VTP)          /* 5376 + 5440 = 10816 */
#define SM_KS(s) (sm_u + (s) * A3S_U32)
#define SM_VS(s) (sm_u + (s) * A3S_U32 + A2N * KVP)
#define SM_P     (sm_u + A3STAGE * A3S_U32)
#define ABAR_OFF ((A3STAGE * A3S_U32 + A2M * PPAD) * 4)   /* 199424 */
#define ATT_SMEM (ABAR_OFF + 64)
#define ATHREADS 512

__global__ __launch_bounds__(ATHREADS, 1)
void attn5_kernel(const uint32_t* __restrict__ gq, const uint32_t* __restrict__ gk,
                  const uint32_t* __restrict__ gvt, uint32_t* __restrict__ outp)
{
    extern __shared__ uint32_t sm_u[];
    const uint32_t sb = (uint32_t)__cvta_generic_to_shared(sm_u);

    const int tid  = threadIdx.x;
    const int lane = tid & 31;
    const int warp = tid >> 5;            /* 0..15 */
    const int qt   = blockIdx.x;
    const int img  = blockIdx.y;
    const int head = blockIdx.z;
    const int sq0  = img * IMG_BLK + qt * A2M;
    const int wq   = warp * 16;
    const int pr   = wq + (lane >> 2);

    /* ldmatrix lane mappings (verified in GEMM) */
    const int bfr = ((lane >> 4) & 1) * 8 + (lane & 7);      /* B-frag row */
    const int bfc = ((lane >> 3) & 1) * 4;                   /* B-frag col */
    const int afr = wq + ((lane >> 3) & 1) * 8 + (lane & 7); /* A-frag row */
    const int afc = (lane >> 4) * 4;                         /* A-frag col */

    const uint32_t fullb  = sb + ABAR_OFF;
    const uint32_t emptyb = sb + ABAR_OFF + 24;

    if (tid == 0) {
#pragma unroll
        for (int s = 0; s < A3STAGE; s++) {
            mbar_init(fullb  + s * 8, ATHREADS);
            mbar_init(emptyb + s * 8, ATHREADS);
        }
    }
    /* Q staging: 256 x 80 u32, stride KVP, aliases stage KV memory */
    {
        const uint32_t* src = gq + ((size_t)head * SEQ + sq0) * HD;
        for (int i = tid; i < A2M * (HD / 4); i += ATHREADS) {
            int r = i / (HD / 4), c4 = (i - r * (HD / 4)) * 4;
            *(uint4*)&sm_u[r * KVP + c4] = *(const uint4*)&src[r * HD + c4];
        }
    }
    __syncthreads();

    uint32_t aq[10][4];
#pragma unroll
    for (int ks = 0; ks < 10; ks++) {
        const int c = ks * 8 + (lane & 3);
        aq[ks][0] = sm_u[pr * KVP + c];
        aq[ks][1] = sm_u[(pr + 8) * KVP + c];
        aq[ks][2] = sm_u[pr * KVP + c + 4];
        aq[ks][3] = sm_u[(pr + 8) * KVP + c + 4];
    }
    __syncthreads();   /* Q frag reads done; KV ring may start */

    const uint32_t* kbase  = gk  + ((size_t)head * SEQ + img * IMG_BLK) * HD;
    const uint32_t* vtbase = gvt + (size_t)head * HD * SEQ + img * IMG_BLK;

    auto produce = [&](int jt, int s) {
        const uint32_t* ks_ = kbase + (size_t)jt * A2N * HD;
        uint32_t* kd = SM_KS(s);
        for (int i = tid; i < A2N * (HD / 4); i += ATHREADS) {
            int r = i / (HD / 4), c4 = (i - r * (HD / 4)) * 4;
            cp_async16(&kd[r * KVP + c4], &ks_[r * HD + c4]);
        }
        const uint32_t* vs_ = vtbase + (size_t)jt * A2N;
        uint32_t* vd = SM_VS(s);
        for (int i = tid; i < HD * (A2N / 4); i += ATHREADS) {
            int r = i / (A2N / 4), c4 = (i - r * (A2N / 4)) * 4;
            cp_async16(&vd[r * VTP + c4], &vs_[(size_t)r * SEQ + c4]);
        }
        cpasync_arrive_noinc(fullb + s * 8);
    };

    float o[10][4];
#pragma unroll
    for (int nt = 0; nt < 10; nt++)
#pragma unroll
        for (int r = 0; r < 4; r++) o[nt][r] = 0.f;
    float m0r = -1e30f, m1r = -1e30f, l0 = 0.f, l1 = 0.f;

    const int NT = IMG_BLK / A2N;   /* 16 */

    int fs = 0, fph = 0;
    int es = 0, eph = 1;

    for (int pj = 0; pj < 2; pj++) {
        mbar_wait(emptyb + es * 8, eph);
        produce(pj, es);
        if (++es == A3STAGE) { es = 0; eph ^= 1; }
    }
    int pj = 2;

#pragma unroll 1
    for (int jt = 0; jt < NT; jt++) {
        mbar_wait(fullb + fs * 8, fph);

        const uint32_t Kbb = sb + (fs * A3S_U32) * 4;
        const uint32_t Vbb = Kbb + A2N * KVP * 4;

        /* ---- S = Q K^T (K frags via ldmatrix) ---- */
        float sacc[8][4];
#pragma unroll
        for (int nt = 0; nt < 8; nt++)
#pragma unroll
            for (int r = 0; r < 4; r++) sacc[nt][r] = 0.f;

#pragma unroll
        for (int ks = 0; ks < 10; ks++) {
#pragma unroll
            for (int p = 0; p < 4; p++) {
                uint32_t bk[4];
                ldsm_x4(bk, Kbb + (((p * 16 + bfr) * KVP + bfc + ks * 8) << 2));
                mma_tf32(sacc[2 * p],     aq[ks], bk);
                mma_tf32(sacc[2 * p + 1], aq[ks], bk + 2);
            }
        }

        /* ---- online softmax (rows warp-private) ---- */
        float mx0 = -1e30f, mx1 = -1e30f;
#pragma unroll
        for (int nt = 0; nt < 8; nt++) {
            mx0 = fmaxf(mx0, fmaxf(sacc[nt][0], sacc[nt][1]));
            mx1 = fmaxf(mx1, fmaxf(sacc[nt][2], sacc[nt][3]));
        }
        mx0 = fmaxf(mx0, __shfl_xor_sync(0xffffffffu, mx0, 1));
        mx0 = fmaxf(mx0, __shfl_xor_sync(0xffffffffu, mx0, 2));
        mx1 = fmaxf(mx1, __shfl_xor_sync(0xffffffffu, mx1, 1));
        mx1 = fmaxf(mx1, __shfl_xor_sync(0xffffffffu, mx1, 2));

        float mn0 = fmaxf(m0r, mx0), mn1 = fmaxf(m1r, mx1);
        float cor0 = __expf(m0r - mn0), cor1 = __expf(m1r - mn1);
        m0r = mn0; m1r = mn1;

        uint32_t* Ps = SM_P;
        float rs0 = 0.f, rs1 = 0.f;
#pragma unroll
        for (int nt = 0; nt < 8; nt++) {
            float p0 = __expf(sacc[nt][0] - mn0);
            float p1 = __expf(sacc[nt][1] - mn0);
            float p2 = __expf(sacc[nt][2] - mn1);
            float p3 = __expf(sacc[nt][3] - mn1);
            rs0 += p0 + p1;  rs1 += p2 + p3;
            int col = nt * 8 + (lane & 3) * 2;
            uint2 u01 = { __float_as_uint(p0) + 0x1000u, __float_as_uint(p1) + 0x1000u };
            *(uint2*)&Ps[pr * PPAD + col] = u01;
            uint2 u23 = { __float_as_uint(p2) + 0x1000u, __float_as_uint(p3) + 0x1000u };
            *(uint2*)&Ps[(pr + 8) * PPAD + col] = u23;
        }
        rs0 += __shfl_xor_sync(0xffffffffu, rs0, 1);
        rs0 += __shfl_xor_sync(0xffffffffu, rs0, 2);
        rs1 += __shfl_xor_sync(0xffffffffu, rs1, 1);
        rs1 += __shfl_xor_sync(0xffffffffu, rs1, 2);
        l0 = l0 * cor0 + rs0;
        l1 = l1 * cor1 + rs1;
#pragma unroll
        for (int nt = 0; nt < 10; nt++) {
            o[nt][0] *= cor0; o[nt][1] *= cor0;
            o[nt][2] *= cor1; o[nt][3] *= cor1;
        }

        __syncwarp();   /* P rows warp-private */

        /* ---- O += P V  (P and Vt frags via ldmatrix) ---- */
        const uint32_t Pbb = sb + (A3STAGE * A3S_U32) * 4;
#pragma unroll
        for (int ks = 0; ks < 8; ks++) {
            uint32_t ap[4];
            ldsm_x4(ap, Pbb + ((afr * PPAD + afc + ks * 8) << 2));
#pragma unroll
            for (int p = 0; p < 5; p++) {
                uint32_t bv[4];
                ldsm_x4(bv, Vbb + (((p * 16 + bfr) * VTP + bfc + ks * 8) << 2));
                mma_tf32(o[2 * p],     ap, bv);
                mma_tf32(o[2 * p + 1], ap, bv + 2);
            }
        }
        __syncwarp();

        mbar_arrive(emptyb + fs * 8);
        if (++fs == A3STAGE) { fs = 0; fph ^= 1; }

        if (pj < NT) {
            mbar_wait(emptyb + es * 8, eph);
            produce(pj, es);
            if (++es == A3STAGE) { es = 0; eph ^= 1; }
            pj++;
        }
    }

    /* normalize + store tf32-pre-rounded bits for the proj GEMM */
    float inv0 = 1.0f / l0, inv1 = 1.0f / l1;
    int srow = sq0 + pr;
#pragma unroll
    for (int nt = 0; nt < 10; nt++) {
        int col = head * HD + nt * 8 + (lane & 3) * 2;
        uint2 v0 = { __float_as_uint(o[nt][0] * inv0) + 0x1000u,
                     __float_as_uint(o[nt][1] * inv0) + 0x1000u };
        *(uint2*)&outp[(size_t)srow * HID + col] = v0;
        uint2 v1 = { __float_as_uint(o[nt][2] * inv1) + 0x1000u,
                     __float_as_uint(o[nt][3] * inv1) + 0x1000u };
        *(uint2*)&outp[(size_t)(srow + 8) * HID + col] = v1;
    }
}

/* ============================== launch =================================== */
extern "C" void kernel_launch(void* const* d_in, const int* in_sizes, int n_in,
                              void* d_out, int out_size)
{
    (void)in_sizes; (void)n_in; (void)out_size;
    const float* hidden = (const float*)d_in[0];
    const float* cosb   = (const float*)d_in[2];
    const float* sinb   = (const float*)d_in[3];
    const float* qkv_w  = (const float*)d_in[4];
    const float* qkv_b  = (const float*)d_in[5];
    const float* proj_w = (const float*)d_in[6];
    const float* proj_b = (const float*)d_in[7];
    float* out = (float*)d_out;

    float *qkv_ptr;
    uint32_t *att_ptr, *qp, *kp, *vtp, *hid_r, *wq_r, *wp_r;
    cudaGetSymbolAddress((void**)&qkv_ptr, g_qkv);
    cudaGetSymbolAddress((void**)&att_ptr, g_att);
    cudaGetSymbolAddress((void**)&qp, g_q);
    cudaGetSymbolAddress((void**)&kp, g_k);
    cudaGetSymbolAddress((void**)&vtp, g_vt);
    cudaGetSymbolAddress((void**)&hid_r, g_hid_r);
    cudaGetSymbolAddress((void**)&wq_r, g_wq_r);
    cudaGetSymbolAddress((void**)&wp_r, g_wp_r);

    cudaFuncSetAttribute(gemm_bias_kernel, cudaFuncAttributeMaxDynamicSharedMemorySize,
                         GEMM_SMEM);
    cudaFuncSetAttribute(attn5_kernel, cudaFuncAttributeMaxDynamicSharedMemorySize,
                         ATT_SMEM);

    /* pre-round all operands (tf32 RN) in one launch */
    round_all_kernel<<<(RN3 + 255) / 256, 256>>>((const uint32_t*)hidden,
                                                 (const uint32_t*)qkv_w,
                                                 (const uint32_t*)proj_w,
                                                 hid_r, wq_r, wp_r);

    dim3 g1(HID3 / GBN, SEQ / GBM);
    gemm_bias_kernel<<<g1, 256, GEMM_SMEM>>>(hid_r, wq_r, qkv_b, qkv_ptr,
                                             SEQ, HID3, HID);

    int total = SEQ * NH * HD;
    prep_kernel<<<(total + 255) / 256, 256>>>(qkv_ptr, cosb, sinb);

    dim3 gv(SEQ / 32, (HD + 31) / 32, NH);
    vtrans_kernel<<<gv, 256>>>(qkv_ptr);

    dim3 ga(IMG_BLK / A2M, 4, NH);
    attn5_kernel<<<ga, ATHREADS, ATT_SMEM>>>(qp, kp, vtp, att_ptr);

    dim3 g3(HID / GBN, SEQ / GBM);
    gemm_bias_kernel<<<g3, 256, GEMM_SMEM>>>(att_ptr, wp_r, proj_b, out,
                                             SEQ, HID, HID);
}